// round 2
// baseline (speedup 1.0000x reference)
#include <cuda_runtime.h>
#include <cstdint>

#define NC     2048
#define D      256
#define NROWS  32768      // 32 * 1024
#define BM     128        // rows per CTA
#define BK     128        // centroids per tile
#define DC     32         // D chunk
#define KSPLIT 4          // centroid range split across blockIdx.y

// Output layout (float32), tuple order of the reference:
//   quantized  [32,1024,256] -> 8388608
//   loss       [32,1024,256] -> 8388608
//   nn_idx     [1,32,1024]   -> 32768   (written as float)
//   codebook   [1,2048,256]  -> 524288
//   new_counts [2048]        -> 2048
#define OFF_Q    0
#define OFF_L    8388608
#define OFF_NN   16777216
#define OFF_CB   16809984
#define OFF_CNT  17334272

// Scratch (allocation-free): device globals
__device__ float              g_cnorm[NC];     // ||c||^2 (full, fp32)
__device__ float              g_srow[NROWS];   // ||x||^2 per row (fp32, sequential order)
__device__ unsigned long long g_best[NROWS];   // packed (sortable score || idx)
__device__ int                g_hist[NC];

// ---------------------------------------------------------------------------
// K0: per-row ||x||^2, fp32, STRICTLY SEQUENTIAL over d=0..255 to replicate
// the reference reduce order (rounded square, then rounded adds).
// one thread per row.
// ---------------------------------------------------------------------------
__global__ void __launch_bounds__(256) srow_kernel(const float* __restrict__ x) {
    int r = blockIdx.x * blockDim.x + threadIdx.x;
    if (r >= NROWS) return;
    const float4* row = (const float4*)(x + (size_t)r * D);
    float s = 0.0f;
#pragma unroll
    for (int q = 0; q < D / 4; q++) {
        float4 v = row[q];
        s = __fadd_rn(s, __fmul_rn(v.x, v.x));
        s = __fadd_rn(s, __fmul_rn(v.y, v.y));
        s = __fadd_rn(s, __fmul_rn(v.z, v.z));
        s = __fadd_rn(s, __fmul_rn(v.w, v.w));
    }
    g_srow[r] = s;
}

// ---------------------------------------------------------------------------
// K1: centroid norms (sequential fp32, same replication) + codebook copy
// + scratch init. One thread per centroid for the norm; warps for the copy.
// ---------------------------------------------------------------------------
__global__ void __launch_bounds__(256) prep_kernel(const float* __restrict__ cb,
                                                   float* __restrict__ outcb) {
    int gid = blockIdx.x * blockDim.x + threadIdx.x;   // 0..65535
    if (gid < NROWS) g_best[gid] = 0xFFFFFFFFFFFFFFFFULL;
    if (gid < NC)    g_hist[gid] = 0;

    // copy codebook: warp per centroid
    int wid  = gid >> 5;
    int lane = gid & 31;
    const float* row  = cb    + (size_t)wid * D;
    float*       orow = outcb + (size_t)wid * D;
#pragma unroll
    for (int j = 0; j < 8; j++) orow[lane + 32 * j] = row[lane + 32 * j];

    // sequential-order norm: first 2048 threads, one centroid each
    if (gid < NC) {
        const float4* crow = (const float4*)(cb + (size_t)gid * D);
        float s = 0.0f;
#pragma unroll
        for (int q = 0; q < D / 4; q++) {
            float4 v = crow[q];
            s = __fadd_rn(s, __fmul_rn(v.x, v.x));
            s = __fadd_rn(s, __fmul_rn(v.y, v.y));
            s = __fadd_rn(s, __fmul_rn(v.z, v.z));
            s = __fadd_rn(s, __fmul_rn(v.w, v.w));
        }
        g_cnorm[gid] = s;
    }
}

// ---------------------------------------------------------------------------
// K2: fused dot-product GEMM + running argmin.
// d(n,k) is an ascending-k fp32 fma chain (matches reference GEMM rounding);
// score = fl( fl(s_n - 2 d) + ||c_k||^2 )  -- exact reference rounding
// pipeline, so ties reproduce; ties break to the smaller index everywhere.
// grid (NROWS/BM, KSPLIT), 256 threads. 8x8 microtile, packed f32x2 FMAs.
// ---------------------------------------------------------------------------
__global__ void __launch_bounds__(256) argmin_kernel(const float* __restrict__ x,
                                                     const float* __restrict__ cb) {
    __shared__ __align__(16) float Xs[DC][BM];
    __shared__ __align__(16) float Cs[DC][BK];

    const int tid = threadIdx.x;
    const int tx  = tid & 15;      // centroid microtile coord
    const int ty  = tid >> 4;      // row microtile coord
    const int rowBase = blockIdx.x * BM;
    const int kBase0  = blockIdx.y * (NC / KSPLIT);

    // loader mapping: each thread loads one row/centroid half-chunk (16 floats)
    const int lr  = tid >> 1;            // row / centroid within tile (0..127)
    const int ldb = (tid & 1) * 16;      // d offset within chunk (0 or 16)

    float s8[8];
#pragma unroll
    for (int i = 0; i < 8; i++) s8[i] = g_srow[rowBase + ty * 8 + i];

    float bestv[8];
    int   besti[8];
#pragma unroll
    for (int i = 0; i < 8; i++) { bestv[i] = 3.4e38f; besti[i] = 0x7FFFFFFF; }

    const int KT = (NC / KSPLIT) / BK;   // 4 centroid tiles per block
    for (int kt = 0; kt < KT; kt++) {
        const int kBase = kBase0 + kt * BK;

        unsigned long long acc[4][8];    // 4 row-pairs x 8 centroids, f32x2
#pragma unroll
        for (int i = 0; i < 4; i++)
#pragma unroll
            for (int j = 0; j < 8; j++) acc[i][j] = 0ULL;

        for (int dc = 0; dc < D; dc += DC) {
            // load X chunk (transposed) and C chunk (transposed)
            const float* xg = x  + (size_t)(rowBase + lr) * D + dc + ldb;
            const float* cg = cb + (size_t)(kBase  + lr) * D + dc + ldb;
#pragma unroll
            for (int q = 0; q < 4; q++) {
                float4 v = *(const float4*)(xg + q * 4);
                Xs[ldb + q * 4 + 0][lr] = v.x;
                Xs[ldb + q * 4 + 1][lr] = v.y;
                Xs[ldb + q * 4 + 2][lr] = v.z;
                Xs[ldb + q * 4 + 3][lr] = v.w;
                float4 w = *(const float4*)(cg + q * 4);
                Cs[ldb + q * 4 + 0][lr] = w.x;
                Cs[ldb + q * 4 + 1][lr] = w.y;
                Cs[ldb + q * 4 + 2][lr] = w.z;
                Cs[ldb + q * 4 + 3][lr] = w.w;
            }
            __syncthreads();

#pragma unroll
            for (int dk = 0; dk < DC; dk++) {
                const float* xr = &Xs[dk][ty * 8];
                ulonglong2 aA = *(const ulonglong2*)(xr);      // rows 0-3 packed
                ulonglong2 aB = *(const ulonglong2*)(xr + 4);  // rows 4-7 packed
                unsigned long long a[4] = {aA.x, aA.y, aB.x, aB.y};

                const float* cr = &Cs[dk][tx * 8];
                float4 b0 = *(const float4*)(cr);
                float4 b1 = *(const float4*)(cr + 4);
                float bs[8] = {b0.x, b0.y, b0.z, b0.w, b1.x, b1.y, b1.z, b1.w};
#pragma unroll
                for (int j = 0; j < 8; j++) {
                    unsigned long long bb;
                    asm("mov.b64 %0, {%1, %1};" : "=l"(bb) : "f"(bs[j]));
#pragma unroll
                    for (int i = 0; i < 4; i++) {
                        asm("fma.rn.f32x2 %0, %1, %2, %0;"
                            : "+l"(acc[i][j]) : "l"(a[i]), "l"(bb));
                    }
                }
            }
            __syncthreads();
        }

        // fold this centroid tile into the running per-row argmin,
        // replicating the reference's two fp32 rounding stages:
        //   t1 = fl(s - 2d)   (fma(-2,d,s) == that exactly, 2d is exact)
        //   score = fl(t1 + cn)
#pragma unroll
        for (int j = 0; j < 8; j++) {
            const int k = kBase + tx * 8 + j;
            const float cn = __ldg(&g_cnorm[k]);
#pragma unroll
            for (int i2 = 0; i2 < 4; i2++) {
                unsigned long long p = acc[i2][j];
                float lo = __uint_as_float((unsigned)(p & 0xFFFFFFFFu));
                float hi = __uint_as_float((unsigned)(p >> 32));
                int i = 2 * i2;
                float s0 = __fadd_rn(__fmaf_rn(-2.0f, lo, s8[i]),     cn);
                float s1 = __fadd_rn(__fmaf_rn(-2.0f, hi, s8[i + 1]), cn);
                if (s0 < bestv[i])     { bestv[i]     = s0; besti[i]     = k; }
                if (s1 < bestv[i + 1]) { bestv[i + 1] = s1; besti[i + 1] = k; }
            }
        }
    }

    // reduce across the 16 threads sharing each row (tx dimension),
    // tie-break toward the smaller index (matches jnp.argmin first-min).
#pragma unroll
    for (int i = 0; i < 8; i++) {
        float v  = bestv[i];
        int   ix = besti[i];
#pragma unroll
        for (int m = 1; m < 16; m <<= 1) {
            float ov = __shfl_xor_sync(0xFFFFFFFFu, v, m);
            int   oi = __shfl_xor_sync(0xFFFFFFFFu, ix, m);
            if (ov < v || (ov == v && oi < ix)) { v = ov; ix = oi; }
        }
        if (tx == 0) {
            int r = rowBase + ty * 8 + i;
            unsigned int b = __float_as_uint(v);
            unsigned int key = (b & 0x80000000u) ? ~b : (b | 0x80000000u);
            unsigned long long pk = ((unsigned long long)key << 32) | (unsigned int)ix;
            atomicMin(&g_best[r], pk);
        }
    }
}

// ---------------------------------------------------------------------------
// K3: gather quantized rows, loss = 1.25*(q-x)^2, nn_idx as float, histogram.
// one warp per row
// ---------------------------------------------------------------------------
__global__ void __launch_bounds__(256) gather_kernel(const float* __restrict__ x,
                                                     const float* __restrict__ cb,
                                                     float* __restrict__ outq,
                                                     float* __restrict__ outl,
                                                     float* __restrict__ outnn) {
    int warp = (blockIdx.x * blockDim.x + threadIdx.x) >> 5;
    int lane = threadIdx.x & 31;
    if (warp >= NROWS) return;

    unsigned long long pk = g_best[warp];
    int idx = (int)(unsigned)(pk & 0xFFFFFFFFULL);
    if (lane == 0) {
        atomicAdd(&g_hist[idx], 1);
        outnn[warp] = (float)idx;
    }
    const float4* crow = (const float4*)(cb   + (size_t)idx  * D);
    const float4* xrow = (const float4*)(x    + (size_t)warp * D);
    float4*       qrow = (float4*)(outq + (size_t)warp * D);
    float4*       lrow = (float4*)(outl + (size_t)warp * D);
#pragma unroll
    for (int q = 0; q < 2; q++) {
        int d4 = lane + q * 32;
        float4 c  = crow[d4];
        float4 xv = xrow[d4];
        qrow[d4] = c;
        float4 L;
        L.x = 1.25f * (c.x - xv.x) * (c.x - xv.x);
        L.y = 1.25f * (c.y - xv.y) * (c.y - xv.y);
        L.z = 1.25f * (c.z - xv.z) * (c.z - xv.z);
        L.w = 1.25f * (c.w - xv.w) * (c.w - xv.w);
        lrow[d4] = L;
    }
}

// ---------------------------------------------------------------------------
// K4: EMA counts finalize (exact integer histogram -> deterministic)
// ---------------------------------------------------------------------------
__global__ void counts_kernel(const float* __restrict__ cc,
                              float* __restrict__ outc) {
    int k = blockIdx.x * blockDim.x + threadIdx.x;
    if (k < NC) outc[k] = 0.99f * cc[k] + 0.01f * (float)g_hist[k];
}

// ---------------------------------------------------------------------------
extern "C" void kernel_launch(void* const* d_in, const int* in_sizes, int n_in,
                              void* d_out, int out_size) {
    const float* x  = (const float*)d_in[0];   // inputs [32,1024,256]
    const float* cb = (const float*)d_in[1];   // codebook [2048,256]
    const float* cc = (const float*)d_in[2];   // cluster_counts [2048]
    float* out = (float*)d_out;

    float* outq   = out + OFF_Q;
    float* outl   = out + OFF_L;
    float* outnn  = out + OFF_NN;
    float* outcb  = out + OFF_CB;
    float* outcnt = out + OFF_CNT;

    srow_kernel<<<NROWS / 256, 256>>>(x);
    prep_kernel<<<256, 256>>>(cb, outcb);

    dim3 g2(NROWS / BM, KSPLIT);
    argmin_kernel<<<g2, 256>>>(x, cb);

    gather_kernel<<<NROWS * 32 / 256, 256>>>(x, cb, outq, outl, outnn);

    counts_kernel<<<(NC + 255) / 256, 256>>>(cc, outcnt);
}

// round 4
// speedup vs baseline: 2.5644x; 2.5644x over previous
#include <cuda_runtime.h>
#include <cuda_bf16.h>
#include <cstdint>

#define NC     2048
#define D      256
#define NROWS  32768
#define BM     128          // rows per CTA in approx kernel
#define CHUNK  64           // centroids per chunk
#define NCHUNK (NC / CHUNK) // 32

// Output layout (float32):
#define OFF_Q    0
#define OFF_L    8388608
#define OFF_NN   16777216
#define OFF_CB   16809984
#define OFF_CNT  17334272

// SMEM map for approx kernel (bytes). x rows / c rows padded: stride 264 bf16 = 528B.
#define SM_CN    0           // float[2048] = 8192
#define SM_X     8192        // 128 * 528 = 67584
#define SM_C0    75776       // 64 * 528 = 33792
#define SM_C1    109568
#define SM_TOTAL 143360

// scratch (allocation-free)
__device__ float          g_cnorm[NC];
__device__ float          g_srow[NROWS];
__device__ __nv_bfloat16  g_cb[NC * D];
__device__ unsigned int   g_cand[NROWS * 4];
__device__ int            g_nn[NROWS];
__device__ int            g_hist[NC];

__device__ __forceinline__ uint32_t smem_u32(const void* p) {
    uint32_t a;
    asm("{ .reg .u64 t; cvta.to.shared.u64 t, %1; cvt.u32.u64 %0, t; }" : "=r"(a) : "l"(p));
    return a;
}

__device__ __forceinline__ void insert4(unsigned long long* t, unsigned long long u) {
    if (u < t[3]) {
        if (u < t[2]) {
            t[3] = t[2];
            if (u < t[1]) {
                t[2] = t[1];
                if (u < t[0]) { t[1] = t[0]; t[0] = u; } else t[1] = u;
            } else t[2] = u;
        } else t[3] = u;
    }
}

// ---------------------------------------------------------------------------
// K0: per-row ||x||^2, strictly sequential fp32 (reference rounding order)
// ---------------------------------------------------------------------------
__global__ void __launch_bounds__(256) srow_kernel(const float* __restrict__ x) {
    int r = blockIdx.x * blockDim.x + threadIdx.x;
    if (r >= NROWS) return;
    const float4* row = (const float4*)(x + (size_t)r * D);
    float s = 0.0f;
#pragma unroll
    for (int q = 0; q < D / 4; q++) {
        float4 v = row[q];
        s = __fadd_rn(s, __fmul_rn(v.x, v.x));
        s = __fadd_rn(s, __fmul_rn(v.y, v.y));
        s = __fadd_rn(s, __fmul_rn(v.z, v.z));
        s = __fadd_rn(s, __fmul_rn(v.w, v.w));
    }
    g_srow[r] = s;
}

// ---------------------------------------------------------------------------
// K1: cnorm (sequential fp32) + codebook copy + bf16 codebook + hist init
// ---------------------------------------------------------------------------
__global__ void __launch_bounds__(256) prep_kernel(const float* __restrict__ cb,
                                                   float* __restrict__ outcb) {
    int gid = blockIdx.x * blockDim.x + threadIdx.x;   // 0..65535
    if (gid < NC) g_hist[gid] = 0;

    // codebook copy: warp per centroid
    int wid  = gid >> 5;
    int lane = gid & 31;
    const float* row  = cb    + (size_t)wid * D;
    float*       orow = outcb + (size_t)wid * D;
#pragma unroll
    for (int j = 0; j < 8; j++) orow[lane + 32 * j] = row[lane + 32 * j];

    if (gid < NC) {
        const float4* crow = (const float4*)(cb + (size_t)gid * D);
        float s = 0.0f;
#pragma unroll
        for (int q = 0; q < D / 4; q++) {
            float4 v = crow[q];
            s = __fadd_rn(s, __fmul_rn(v.x, v.x));
            s = __fadd_rn(s, __fmul_rn(v.y, v.y));
            s = __fadd_rn(s, __fmul_rn(v.z, v.z));
            s = __fadd_rn(s, __fmul_rn(v.w, v.w));
        }
        g_cnorm[gid] = s;
    }

    // bf16 codebook: 8 floats/thread (NC*D/8 = 65536)
    {
        const float4* src = (const float4*)cb;
        float4 v0 = src[gid * 2], v1 = src[gid * 2 + 1];
        __nv_bfloat16 b[8];
        b[0] = __float2bfloat16(v0.x); b[1] = __float2bfloat16(v0.y);
        b[2] = __float2bfloat16(v0.z); b[3] = __float2bfloat16(v0.w);
        b[4] = __float2bfloat16(v1.x); b[5] = __float2bfloat16(v1.y);
        b[6] = __float2bfloat16(v1.z); b[7] = __float2bfloat16(v1.w);
        ((uint4*)g_cb)[gid] = *(uint4*)b;
    }
}

// cp.async one 64-centroid bf16 chunk into smem (row stride 528B)
__device__ __forceinline__ void stage_c(uint32_t dst, int cbase, int tid) {
    const char* src = (const char*)(g_cb + (size_t)cbase * D);
#pragma unroll
    for (int i = 0; i < 8; i++) {
        int idx = tid + i * 256;
        int r = idx >> 5, kp = (idx & 31) * 16;
        uint32_t d = dst + (uint32_t)(r * 528 + kp);
        const char* s = src + r * 512 + kp;
        asm volatile("cp.async.ca.shared.global [%0], [%1], 16;" :: "r"(d), "l"(s));
    }
}

// ---------------------------------------------------------------------------
// K2: HMMA bf16 approx GEMM + fused per-row top-4 candidates.
// CTA: 128 rows x all 2048 centroids. Warp w owns rows [w*16, w*16+16).
// A frags in registers (ldmatrix from staged x_sm), C chunks double-buffered.
// ---------------------------------------------------------------------------
__global__ void __launch_bounds__(256, 1) approx_kernel(const float* __restrict__ x) {
    extern __shared__ char sm[];
    float* cn_sm = (float*)(sm + SM_CN);
    const int tid  = threadIdx.x;
    const int lane = tid & 31;
    const int w    = tid >> 5;
    const int rowBase = blockIdx.x * BM;
    const uint32_t smb = smem_u32(sm);
    const uint32_t xb  = smb + SM_X;
    const uint32_t cbA0 = smb + SM_C0, cbA1 = smb + SM_C1;

    for (int i = tid; i < NC; i += 256) cn_sm[i] = g_cnorm[i];

    // stage X (fp32 -> bf16) into x_sm
#pragma unroll
    for (int i = 0; i < 16; i++) {
        int idx = tid + i * 256;
        int r = idx >> 5, kp = (idx & 31) * 8;
        const float4* src = (const float4*)(x + (size_t)(rowBase + r) * D + kp);
        float4 v0 = src[0], v1 = src[1];
        __nv_bfloat16 b[8];
        b[0] = __float2bfloat16(v0.x); b[1] = __float2bfloat16(v0.y);
        b[2] = __float2bfloat16(v0.z); b[3] = __float2bfloat16(v0.w);
        b[4] = __float2bfloat16(v1.x); b[5] = __float2bfloat16(v1.y);
        b[6] = __float2bfloat16(v1.z); b[7] = __float2bfloat16(v1.w);
        *(uint4*)(sm + SM_X + r * 528 + kp * 2) = *(uint4*)b;
    }
    // prologue: chunk 0
    stage_c(cbA0, 0, tid);
    asm volatile("cp.async.commit_group;" ::: "memory");
    __syncthreads();

    // A fragments: 16 k-blocks, ldmatrix.x4 each (m16k16)
    uint32_t a[16][4];
#pragma unroll
    for (int kb = 0; kb < 16; kb++) {
        uint32_t addr = xb + (uint32_t)((w * 16 + (lane & 15)) * 528
                                        + (kb * 16 + (lane >> 4) * 8) * 2);
        asm volatile("ldmatrix.sync.aligned.m8n8.x4.shared.b16 {%0,%1,%2,%3}, [%4];"
                     : "=r"(a[kb][0]), "=r"(a[kb][1]), "=r"(a[kb][2]), "=r"(a[kb][3])
                     : "r"(addr));
    }

    unsigned long long top[2][4];
#pragma unroll
    for (int h = 0; h < 2; h++)
#pragma unroll
        for (int j = 0; j < 4; j++) top[h][j] = 0xFFFFFFFFFFFFFFFFULL;

    for (int ch = 0; ch < NCHUNK; ch++) {
        if (ch + 1 < NCHUNK) {
            stage_c(((ch + 1) & 1) ? cbA1 : cbA0, (ch + 1) * CHUNK, tid);
            asm volatile("cp.async.commit_group;" ::: "memory");
            asm volatile("cp.async.wait_group 1;" ::: "memory");
        } else {
            asm volatile("cp.async.wait_group 0;" ::: "memory");
        }
        __syncthreads();

        const uint32_t cbB = (ch & 1) ? cbA1 : cbA0;
        float acc[8][4];
#pragma unroll
        for (int nt = 0; nt < 8; nt++)
#pragma unroll
            for (int e = 0; e < 4; e++) acc[nt][e] = 0.0f;

#pragma unroll
        for (int kb = 0; kb < 16; kb++) {
#pragma unroll
            for (int np = 0; np < 4; np++) {
                uint32_t addr = cbB + (uint32_t)((np * 16 + (lane & 7) + (lane >> 4) * 8) * 528
                                                 + (kb * 16 + ((lane >> 3) & 1) * 8) * 2);
                uint32_t b0, b1, b2, b3;
                asm volatile("ldmatrix.sync.aligned.m8n8.x4.shared.b16 {%0,%1,%2,%3}, [%4];"
                             : "=r"(b0), "=r"(b1), "=r"(b2), "=r"(b3) : "r"(addr));
                asm volatile("mma.sync.aligned.m16n8k16.row.col.f32.bf16.bf16.f32 "
                             "{%0,%1,%2,%3}, {%4,%5,%6,%7}, {%8,%9}, {%0,%1,%2,%3};"
                             : "+f"(acc[np*2][0]), "+f"(acc[np*2][1]),
                               "+f"(acc[np*2][2]), "+f"(acc[np*2][3])
                             : "r"(a[kb][0]), "r"(a[kb][1]), "r"(a[kb][2]), "r"(a[kb][3]),
                               "r"(b0), "r"(b1));
                asm volatile("mma.sync.aligned.m16n8k16.row.col.f32.bf16.bf16.f32 "
                             "{%0,%1,%2,%3}, {%4,%5,%6,%7}, {%8,%9}, {%0,%1,%2,%3};"
                             : "+f"(acc[np*2+1][0]), "+f"(acc[np*2+1][1]),
                               "+f"(acc[np*2+1][2]), "+f"(acc[np*2+1][3])
                             : "r"(a[kb][0]), "r"(a[kb][1]), "r"(a[kb][2]), "r"(a[kb][3]),
                               "r"(b2), "r"(b3));
            }
        }

        // epilogue: approx score = cn - 2d ; track per-thread top-4
        int kbase = ch * CHUNK + (lane & 3) * 2;
#pragma unroll
        for (int nt = 0; nt < 8; nt++) {
#pragma unroll
            for (int e = 0; e < 4; e++) {
                int k = kbase + nt * 8 + (e & 1);
                float sc = __fmaf_rn(-2.0f, acc[nt][e], cn_sm[k]);
                uint32_t bb = __float_as_uint(sc);
                uint32_t key = (bb & 0x80000000u) ? ~bb : (bb | 0x80000000u);
                unsigned long long u = ((unsigned long long)key << 32) | (uint32_t)k;
                insert4(top[e >> 1], u);
            }
        }
        __syncthreads();   // protect buffer before next overwrite
    }

    // merge top-4 across the 4 lanes sharing each row (bitonic), write candidates
#pragma unroll
    for (int h = 0; h < 2; h++) {
        unsigned long long v0 = top[h][0], v1 = top[h][1], v2 = top[h][2], v3 = top[h][3];
#pragma unroll
        for (int m = 1; m <= 2; m <<= 1) {
            unsigned long long o0 = __shfl_xor_sync(0xFFFFFFFFu, v0, m);
            unsigned long long o1 = __shfl_xor_sync(0xFFFFFFFFu, v1, m);
            unsigned long long o2 = __shfl_xor_sync(0xFFFFFFFFu, v2, m);
            unsigned long long o3 = __shfl_xor_sync(0xFFFFFFFFu, v3, m);
            unsigned long long s0 = v0 < o3 ? v0 : o3;
            unsigned long long s1 = v1 < o2 ? v1 : o2;
            unsigned long long s2 = v2 < o1 ? v2 : o1;
            unsigned long long s3 = v3 < o0 ? v3 : o0;
            unsigned long long a0 = s0 < s2 ? s0 : s2, a2 = s0 < s2 ? s2 : s0;
            unsigned long long a1 = s1 < s3 ? s1 : s3, a3 = s1 < s3 ? s3 : s1;
            v0 = a0 < a1 ? a0 : a1; v1 = a0 < a1 ? a1 : a0;
            v2 = a2 < a3 ? a2 : a3; v3 = a2 < a3 ? a3 : a2;
        }
        if ((lane & 3) == 0) {
            int row = rowBase + w * 16 + (lane >> 2) + h * 8;
            uint4 st;
            st.x = (uint32_t)v0; st.y = (uint32_t)v1;
            st.z = (uint32_t)v2; st.w = (uint32_t)v3;
            *(uint4*)&g_cand[row * 4] = st;
        }
    }
}

// ---------------------------------------------------------------------------
// K3: exact rescore of 4 candidates per row (reference rounding pipeline).
// warp per row; lanes 0-3 compute exact d chains; score with g_srow/g_cnorm.
// ---------------------------------------------------------------------------
__global__ void __launch_bounds__(128) rescore_kernel(const float* __restrict__ x,
                                                      const float* __restrict__ cb) {
    int row  = (blockIdx.x * blockDim.x + threadIdx.x) >> 5;
    int lane = threadIdx.x & 31;
    if (row >= NROWS) return;

    unsigned long long best = 0xFFFFFFFFFFFFFFFFULL;
    if (lane < 4) {
        unsigned int cand = g_cand[row * 4 + lane];
        const float4* c4 = (const float4*)(cb + (size_t)cand * D);
        const float4* x4 = (const float4*)(x + (size_t)row * D);
        float d = 0.0f;
#pragma unroll 8
        for (int q = 0; q < D / 4; q++) {
            float4 cv = c4[q];
            float4 xv = x4[q];
            d = __fmaf_rn(xv.x, cv.x, d);
            d = __fmaf_rn(xv.y, cv.y, d);
            d = __fmaf_rn(xv.z, cv.z, d);
            d = __fmaf_rn(xv.w, cv.w, d);
        }
        float s  = g_srow[row];
        float sc = __fadd_rn(__fmaf_rn(-2.0f, d, s), g_cnorm[cand]);
        uint32_t bb  = __float_as_uint(sc);
        uint32_t key = (bb & 0x80000000u) ? ~bb : (bb | 0x80000000u);
        best = ((unsigned long long)key << 32) | cand;
    }
    __syncwarp();
    unsigned long long o;
    o = __shfl_xor_sync(0xFFFFFFFFu, best, 1); best = o < best ? o : best;
    o = __shfl_xor_sync(0xFFFFFFFFu, best, 2); best = o < best ? o : best;
    if (lane == 0) g_nn[row] = (int)(uint32_t)best;
}

// ---------------------------------------------------------------------------
// K4: gather quantized rows, loss, nn_idx (float), histogram. one warp/row.
// ---------------------------------------------------------------------------
__global__ void __launch_bounds__(256) gather_kernel(const float* __restrict__ x,
                                                     const float* __restrict__ cb,
                                                     float* __restrict__ outq,
                                                     float* __restrict__ outl,
                                                     float* __restrict__ outnn) {
    int warp = (blockIdx.x * blockDim.x + threadIdx.x) >> 5;
    int lane = threadIdx.x & 31;
    if (warp >= NROWS) return;

    int idx = g_nn[warp];
    if (lane == 0) {
        atomicAdd(&g_hist[idx], 1);
        outnn[warp] = (float)idx;
    }
    const float4* crow = (const float4*)(cb + (size_t)idx * D);
    const float4* xrow = (const float4*)(x + (size_t)warp * D);
    float4* qrow = (float4*)(outq + (size_t)warp * D);
    float4* lrow = (float4*)(outl + (size_t)warp * D);
#pragma unroll
    for (int q = 0; q < 2; q++) {
        int d4 = lane + q * 32;
        float4 c  = crow[d4];
        float4 xv = xrow[d4];
        qrow[d4] = c;
        float4 L;
        L.x = 1.25f * (c.x - xv.x) * (c.x - xv.x);
        L.y = 1.25f * (c.y - xv.y) * (c.y - xv.y);
        L.z = 1.25f * (c.z - xv.z) * (c.z - xv.z);
        L.w = 1.25f * (c.w - xv.w) * (c.w - xv.w);
        lrow[d4] = L;
    }
}

// K5: EMA counts
__global__ void counts_kernel(const float* __restrict__ cc, float* __restrict__ outc) {
    int k = blockIdx.x * blockDim.x + threadIdx.x;
    if (k < NC) outc[k] = 0.99f * cc[k] + 0.01f * (float)g_hist[k];
}

// ---------------------------------------------------------------------------
extern "C" void kernel_launch(void* const* d_in, const int* in_sizes, int n_in,
                              void* d_out, int out_size) {
    const float* x  = (const float*)d_in[0];
    const float* cb = (const float*)d_in[1];
    const float* cc = (const float*)d_in[2];
    float* out = (float*)d_out;

    cudaFuncSetAttribute(approx_kernel,
                         cudaFuncAttributeMaxDynamicSharedMemorySize, SM_TOTAL);

    srow_kernel<<<NROWS / 256, 256>>>(x);
    prep_kernel<<<256, 256>>>(cb, out + OFF_CB);
    approx_kernel<<<NROWS / BM, 256, SM_TOTAL>>>(x);
    rescore_kernel<<<NROWS * 32 / 128, 128>>>(x, cb);
    gather_kernel<<<NROWS * 32 / 256, 256>>>(x, cb, out + OFF_Q, out + OFF_L, out + OFF_NN);
    counts_kernel<<<(NC + 255) / 256, 256>>>(cc, out + OFF_CNT);
}

// round 5
// speedup vs baseline: 3.1044x; 1.2106x over previous
#include <cuda_runtime.h>
#include <cuda_bf16.h>
#include <cstdint>

#define NC     2048
#define D      256
#define NROWS  32768
#define BM     128          // rows per CTA in approx kernel
#define CHUNK  32           // centroids per chunk
#define NCHUNK (NC / CHUNK) // 64

// Output layout (float32):
#define OFF_Q    0
#define OFF_L    8388608
#define OFF_NN   16777216
#define OFF_CB   16809984
#define OFF_CNT  17334272

// SMEM map (bytes). rows padded: stride 264 bf16 = 528B.
#define SM_CN    0            // float[2048] = 8192
#define SM_X     8192         // 128 * 528 = 67584
#define SM_C0    75776        // 32 * 528 = 16896
#define SM_C1    92672
#define SM_TOTAL 109568       // <= 113.5KB -> 2 CTAs/SM

// scratch (allocation-free)
__device__ float          g_cnorm[NC];
__device__ float          g_srow[NROWS];
__device__ __nv_bfloat16  g_cb[NC * D];
__device__ unsigned int   g_cand[NROWS * 4];
__device__ int            g_nn[NROWS];
__device__ int            g_hist[NC];

__device__ __forceinline__ uint32_t smem_u32(const void* p) {
    uint32_t a;
    asm("{ .reg .u64 t; cvta.to.shared.u64 t, %1; cvt.u32.u64 %0, t; }" : "=r"(a) : "l"(p));
    return a;
}

__device__ __forceinline__ void insert4(unsigned long long* t, unsigned long long u) {
    if (u < t[3]) {
        if (u < t[2]) {
            t[3] = t[2];
            if (u < t[1]) {
                t[2] = t[1];
                if (u < t[0]) { t[1] = t[0]; t[0] = u; } else t[1] = u;
            } else t[2] = u;
        } else t[3] = u;
    }
}

// ---------------------------------------------------------------------------
// K0: per-row ||x||^2, strictly sequential fp32 (reference rounding order)
// ---------------------------------------------------------------------------
__global__ void __launch_bounds__(256) srow_kernel(const float* __restrict__ x) {
    int r = blockIdx.x * blockDim.x + threadIdx.x;
    if (r >= NROWS) return;
    const float4* row = (const float4*)(x + (size_t)r * D);
    float s = 0.0f;
#pragma unroll
    for (int q = 0; q < D / 4; q++) {
        float4 v = row[q];
        s = __fadd_rn(s, __fmul_rn(v.x, v.x));
        s = __fadd_rn(s, __fmul_rn(v.y, v.y));
        s = __fadd_rn(s, __fmul_rn(v.z, v.z));
        s = __fadd_rn(s, __fmul_rn(v.w, v.w));
    }
    g_srow[r] = s;
}

// ---------------------------------------------------------------------------
// K1: cnorm (sequential fp32) + codebook copy + bf16 codebook + hist init
// ---------------------------------------------------------------------------
__global__ void __launch_bounds__(256) prep_kernel(const float* __restrict__ cb,
                                                   float* __restrict__ outcb) {
    int gid = blockIdx.x * blockDim.x + threadIdx.x;   // 0..65535
    if (gid < NC) g_hist[gid] = 0;

    int wid  = gid >> 5;
    int lane = gid & 31;
    const float* row  = cb    + (size_t)wid * D;
    float*       orow = outcb + (size_t)wid * D;
#pragma unroll
    for (int j = 0; j < 8; j++) orow[lane + 32 * j] = row[lane + 32 * j];

    if (gid < NC) {
        const float4* crow = (const float4*)(cb + (size_t)gid * D);
        float s = 0.0f;
#pragma unroll
        for (int q = 0; q < D / 4; q++) {
            float4 v = crow[q];
            s = __fadd_rn(s, __fmul_rn(v.x, v.x));
            s = __fadd_rn(s, __fmul_rn(v.y, v.y));
            s = __fadd_rn(s, __fmul_rn(v.z, v.z));
            s = __fadd_rn(s, __fmul_rn(v.w, v.w));
        }
        g_cnorm[gid] = s;
    }

    // bf16 codebook: 8 floats/thread
    {
        const float4* src = (const float4*)cb;
        float4 v0 = src[gid * 2], v1 = src[gid * 2 + 1];
        __nv_bfloat16 b[8];
        b[0] = __float2bfloat16(v0.x); b[1] = __float2bfloat16(v0.y);
        b[2] = __float2bfloat16(v0.z); b[3] = __float2bfloat16(v0.w);
        b[4] = __float2bfloat16(v1.x); b[5] = __float2bfloat16(v1.y);
        b[6] = __float2bfloat16(v1.z); b[7] = __float2bfloat16(v1.w);
        ((uint4*)g_cb)[gid] = *(uint4*)b;
    }
}

// cp.async one 32-centroid bf16 chunk into smem (row stride 528B)
__device__ __forceinline__ void stage_c(uint32_t dst, int cbase, int tid) {
    const char* src = (const char*)(g_cb + (size_t)cbase * D);
#pragma unroll
    for (int i = 0; i < 4; i++) {
        int idx = tid + i * 256;              // 0..1023
        int r = idx >> 5, kp = (idx & 31) * 16;
        uint32_t d = dst + (uint32_t)(r * 528 + kp);
        const char* s = src + r * 512 + kp;
        asm volatile("cp.async.ca.shared.global [%0], [%1], 16;" :: "r"(d), "l"(s));
    }
}

// ---------------------------------------------------------------------------
// K2: HMMA bf16 approx GEMM + fused per-row top-4. 2 CTAs/SM.
// CTA: 128 rows x 2048 centroids. Warp w owns rows [w*16, w*16+16).
// ---------------------------------------------------------------------------
__global__ void __launch_bounds__(256, 2) approx_kernel(const float* __restrict__ x) {
    extern __shared__ char sm[];
    float* cn_sm = (float*)(sm + SM_CN);
    const int tid  = threadIdx.x;
    const int lane = tid & 31;
    const int w    = tid >> 5;
    const int rowBase = blockIdx.x * BM;
    const uint32_t smb = smem_u32(sm);
    const uint32_t xb  = smb + SM_X;
    const uint32_t cbA0 = smb + SM_C0, cbA1 = smb + SM_C1;

    for (int i = tid; i < NC; i += 256) cn_sm[i] = g_cnorm[i];

    // stage X (fp32 -> bf16) into x_sm
#pragma unroll
    for (int i = 0; i < 16; i++) {
        int idx = tid + i * 256;
        int r = idx >> 5, kp = (idx & 31) * 8;
        const float4* src = (const float4*)(x + (size_t)(rowBase + r) * D + kp);
        float4 v0 = src[0], v1 = src[1];
        __nv_bfloat16 b[8];
        b[0] = __float2bfloat16(v0.x); b[1] = __float2bfloat16(v0.y);
        b[2] = __float2bfloat16(v0.z); b[3] = __float2bfloat16(v0.w);
        b[4] = __float2bfloat16(v1.x); b[5] = __float2bfloat16(v1.y);
        b[6] = __float2bfloat16(v1.z); b[7] = __float2bfloat16(v1.w);
        *(uint4*)(sm + SM_X + r * 528 + kp * 2) = *(uint4*)b;
    }
    stage_c(cbA0, 0, tid);
    asm volatile("cp.async.commit_group;" ::: "memory");
    __syncthreads();

    // A fragments held in regs: 16 k-blocks (m16k16 each)
    uint32_t a[16][4];
#pragma unroll
    for (int kb = 0; kb < 16; kb++) {
        uint32_t addr = xb + (uint32_t)((w * 16 + (lane & 15)) * 528
                                        + (kb * 16 + (lane >> 4) * 8) * 2);
        asm volatile("ldmatrix.sync.aligned.m8n8.x4.shared.b16 {%0,%1,%2,%3}, [%4];"
                     : "=r"(a[kb][0]), "=r"(a[kb][1]), "=r"(a[kb][2]), "=r"(a[kb][3])
                     : "r"(addr));
    }

    unsigned long long top[2][4];
#pragma unroll
    for (int h = 0; h < 2; h++)
#pragma unroll
        for (int j = 0; j < 4; j++) top[h][j] = 0xFFFFFFFFFFFFFFFFULL;

    for (int ch = 0; ch < NCHUNK; ch++) {
        if (ch + 1 < NCHUNK) {
            stage_c(((ch + 1) & 1) ? cbA1 : cbA0, (ch + 1) * CHUNK, tid);
            asm volatile("cp.async.commit_group;" ::: "memory");
            asm volatile("cp.async.wait_group 1;" ::: "memory");
        } else {
            asm volatile("cp.async.wait_group 0;" ::: "memory");
        }
        __syncthreads();

        const uint32_t cbB = (ch & 1) ? cbA1 : cbA0;
        float acc[4][4];
#pragma unroll
        for (int nt = 0; nt < 4; nt++)
#pragma unroll
            for (int e = 0; e < 4; e++) acc[nt][e] = 0.0f;

#pragma unroll
        for (int kb = 0; kb < 16; kb++) {
#pragma unroll
            for (int np = 0; np < 2; np++) {
                uint32_t addr = cbB + (uint32_t)((np * 16 + (lane & 7) + (lane >> 4) * 8) * 528
                                                 + (kb * 16 + ((lane >> 3) & 1) * 8) * 2);
                uint32_t b0, b1, b2, b3;
                asm volatile("ldmatrix.sync.aligned.m8n8.x4.shared.b16 {%0,%1,%2,%3}, [%4];"
                             : "=r"(b0), "=r"(b1), "=r"(b2), "=r"(b3) : "r"(addr));
                asm volatile("mma.sync.aligned.m16n8k16.row.col.f32.bf16.bf16.f32 "
                             "{%0,%1,%2,%3}, {%4,%5,%6,%7}, {%8,%9}, {%0,%1,%2,%3};"
                             : "+f"(acc[np*2][0]), "+f"(acc[np*2][1]),
                               "+f"(acc[np*2][2]), "+f"(acc[np*2][3])
                             : "r"(a[kb][0]), "r"(a[kb][1]), "r"(a[kb][2]), "r"(a[kb][3]),
                               "r"(b0), "r"(b1));
                asm volatile("mma.sync.aligned.m16n8k16.row.col.f32.bf16.bf16.f32 "
                             "{%0,%1,%2,%3}, {%4,%5,%6,%7}, {%8,%9}, {%0,%1,%2,%3};"
                             : "+f"(acc[np*2+1][0]), "+f"(acc[np*2+1][1]),
                               "+f"(acc[np*2+1][2]), "+f"(acc[np*2+1][3])
                             : "r"(a[kb][0]), "r"(a[kb][1]), "r"(a[kb][2]), "r"(a[kb][3]),
                               "r"(b2), "r"(b3));
            }
        }

        // epilogue: approx score = cn - 2d ; per-thread top-4
        int kbase = ch * CHUNK + (lane & 3) * 2;
#pragma unroll
        for (int nt = 0; nt < 4; nt++) {
#pragma unroll
            for (int e = 0; e < 4; e++) {
                int k = kbase + nt * 8 + (e & 1);
                float sc = __fmaf_rn(-2.0f, acc[nt][e], cn_sm[k]);
                uint32_t bb = __float_as_uint(sc);
                uint32_t key = (bb & 0x80000000u) ? ~bb : (bb | 0x80000000u);
                unsigned long long u = ((unsigned long long)key << 32) | (uint32_t)k;
                insert4(top[e >> 1], u);
            }
        }
        __syncthreads();
    }

    // merge top-4 across the 4 lanes sharing each row, write candidates
#pragma unroll
    for (int h = 0; h < 2; h++) {
        unsigned long long v0 = top[h][0], v1 = top[h][1], v2 = top[h][2], v3 = top[h][3];
#pragma unroll
        for (int m = 1; m <= 2; m <<= 1) {
            unsigned long long o0 = __shfl_xor_sync(0xFFFFFFFFu, v0, m);
            unsigned long long o1 = __shfl_xor_sync(0xFFFFFFFFu, v1, m);
            unsigned long long o2 = __shfl_xor_sync(0xFFFFFFFFu, v2, m);
            unsigned long long o3 = __shfl_xor_sync(0xFFFFFFFFu, v3, m);
            unsigned long long s0 = v0 < o3 ? v0 : o3;
            unsigned long long s1 = v1 < o2 ? v1 : o2;
            unsigned long long s2 = v2 < o1 ? v2 : o1;
            unsigned long long s3 = v3 < o0 ? v3 : o0;
            unsigned long long a0 = s0 < s2 ? s0 : s2, a2 = s0 < s2 ? s2 : s0;
            unsigned long long a1 = s1 < s3 ? s1 : s3, a3 = s1 < s3 ? s3 : s1;
            v0 = a0 < a1 ? a0 : a1; v1 = a0 < a1 ? a1 : a0;
            v2 = a2 < a3 ? a2 : a3; v3 = a2 < a3 ? a3 : a2;
        }
        if ((lane & 3) == 0) {
            int row = rowBase + w * 16 + (lane >> 2) + h * 8;
            uint4 st;
            st.x = (uint32_t)v0; st.y = (uint32_t)v1;
            st.z = (uint32_t)v2; st.w = (uint32_t)v3;
            *(uint4*)&g_cand[row * 4] = st;
        }
    }
}

// ---------------------------------------------------------------------------
// K3: exact rescore, all 32 lanes. warp = row; lane = (cand = lane>>3,
// seg = lane&7). Each lane chains 32 contiguous elems; fixed butterfly tree
// within the 8-lane group; min across candidate groups with packed keys.
// ---------------------------------------------------------------------------
__global__ void __launch_bounds__(256) rescore_kernel(const float* __restrict__ x,
                                                      const float* __restrict__ cb) {
    int row  = (blockIdx.x * blockDim.x + threadIdx.x) >> 5;
    int lane = threadIdx.x & 31;
    if (row >= NROWS) return;
    int c = lane >> 3, s = lane & 7;

    unsigned int cand = g_cand[row * 4 + c];
    const float4* c4 = (const float4*)(cb + (size_t)cand * D) + s * 8;
    const float4* x4 = (const float4*)(x + (size_t)row * D) + s * 8;

    float d = 0.0f;
#pragma unroll
    for (int q = 0; q < 8; q++) {
        float4 cv = c4[q];
        float4 xv = x4[q];
        d = __fmaf_rn(xv.x, cv.x, d);
        d = __fmaf_rn(xv.y, cv.y, d);
        d = __fmaf_rn(xv.z, cv.z, d);
        d = __fmaf_rn(xv.w, cv.w, d);
    }
    // fixed-order tree within 8-lane group
    d = __fadd_rn(d, __shfl_xor_sync(0xFFFFFFFFu, d, 1));
    d = __fadd_rn(d, __shfl_xor_sync(0xFFFFFFFFu, d, 2));
    d = __fadd_rn(d, __shfl_xor_sync(0xFFFFFFFFu, d, 4));

    float sc = __fadd_rn(__fmaf_rn(-2.0f, d, g_srow[row]), g_cnorm[cand]);
    uint32_t bb  = __float_as_uint(sc);
    uint32_t key = (bb & 0x80000000u) ? ~bb : (bb | 0x80000000u);
    unsigned long long best = ((unsigned long long)key << 32) | cand;

    unsigned long long o;
    o = __shfl_xor_sync(0xFFFFFFFFu, best, 8);  best = o < best ? o : best;
    o = __shfl_xor_sync(0xFFFFFFFFu, best, 16); best = o < best ? o : best;
    if (lane == 0) g_nn[row] = (int)(uint32_t)best;
}

// ---------------------------------------------------------------------------
// K4: gather quantized rows, loss, nn_idx (float), histogram. one warp/row.
// ---------------------------------------------------------------------------
__global__ void __launch_bounds__(256) gather_kernel(const float* __restrict__ x,
                                                     const float* __restrict__ cb,
                                                     float* __restrict__ outq,
                                                     float* __restrict__ outl,
                                                     float* __restrict__ outnn) {
    int warp = (blockIdx.x * blockDim.x + threadIdx.x) >> 5;
    int lane = threadIdx.x & 31;
    if (warp >= NROWS) return;

    int idx = g_nn[warp];
    if (lane == 0) {
        atomicAdd(&g_hist[idx], 1);
        outnn[warp] = (float)idx;
    }
    const float4* crow = (const float4*)(cb + (size_t)idx * D);
    const float4* xrow = (const float4*)(x + (size_t)warp * D);
    float4* qrow = (float4*)(outq + (size_t)warp * D);
    float4* lrow = (float4*)(outl + (size_t)warp * D);
#pragma unroll
    for (int q = 0; q < 2; q++) {
        int d4 = lane + q * 32;
        float4 cv = crow[d4];
        float4 xv = xrow[d4];
        qrow[d4] = cv;
        float4 L;
        L.x = 1.25f * (cv.x - xv.x) * (cv.x - xv.x);
        L.y = 1.25f * (cv.y - xv.y) * (cv.y - xv.y);
        L.z = 1.25f * (cv.z - xv.z) * (cv.z - xv.z);
        L.w = 1.25f * (cv.w - xv.w) * (cv.w - xv.w);
        lrow[d4] = L;
    }
}

// K5: EMA counts
__global__ void counts_kernel(const float* __restrict__ cc, float* __restrict__ outc) {
    int k = blockIdx.x * blockDim.x + threadIdx.x;
    if (k < NC) outc[k] = 0.99f * cc[k] + 0.01f * (float)g_hist[k];
}

// ---------------------------------------------------------------------------
extern "C" void kernel_launch(void* const* d_in, const int* in_sizes, int n_in,
                              void* d_out, int out_size) {
    const float* x  = (const float*)d_in[0];
    const float* cb = (const float*)d_in[1];
    const float* cc = (const float*)d_in[2];
    float* out = (float*)d_out;

    cudaFuncSetAttribute(approx_kernel,
                         cudaFuncAttributeMaxDynamicSharedMemorySize, SM_TOTAL);

    srow_kernel<<<NROWS / 256, 256>>>(x);
    prep_kernel<<<256, 256>>>(cb, out + OFF_CB);
    approx_kernel<<<NROWS / BM, 256, SM_TOTAL>>>(x);
    rescore_kernel<<<NROWS * 32 / 256, 256>>>(x, cb);
    gather_kernel<<<NROWS * 32 / 256, 256>>>(x, cb, out + OFF_Q, out + OFF_L, out + OFF_NN);
    counts_kernel<<<(NC + 255) / 256, 256>>>(cc, out + OFF_CNT);
}

// round 6
// speedup vs baseline: 3.8593x; 1.2432x over previous
#include <cuda_runtime.h>
#include <cuda_bf16.h>
#include <cstdint>

#define NC     2048
#define D      256
#define NROWS  32768
#define BM     128          // rows per CTA in approx kernel
#define CHUNK  32           // centroids per chunk
#define NCHUNK (NC / CHUNK) // 64

// Output layout (float32):
#define OFF_Q    0
#define OFF_L    8388608
#define OFF_NN   16777216
#define OFF_CB   16809984
#define OFF_CNT  17334272

// SMEM map (bytes). rows padded: stride 264 bf16 = 528B.
#define SM_CN    0            // float[2048] = 8192
#define SM_X     8192         // 128 * 528 = 67584
#define SM_C0    75776        // 32 * 528 = 16896
#define SM_C1    92672
#define SM_TOTAL 109568       // <= 113.5KB -> 2 CTAs/SM

// scratch (allocation-free)
__device__ float          g_cnorm[NC];
__device__ float          g_srow[NROWS];
__device__ __nv_bfloat16  g_cb[NC * D];
__device__ unsigned int   g_cand[NROWS * 4];
__device__ int            g_hist[NC];

__device__ __forceinline__ uint32_t smem_u32(const void* p) {
    uint32_t a;
    asm("{ .reg .u64 t; cvta.to.shared.u64 t, %1; cvt.u32.u64 %0, t; }" : "=r"(a) : "l"(p));
    return a;
}

__device__ __forceinline__ void insert4(unsigned long long* t, unsigned long long u) {
    if (u < t[3]) {
        if (u < t[2]) {
            t[3] = t[2];
            if (u < t[1]) {
                t[2] = t[1];
                if (u < t[0]) { t[1] = t[0]; t[0] = u; } else t[1] = u;
            } else t[2] = u;
        } else t[3] = u;
    }
}

// ---------------------------------------------------------------------------
// K0: per-row ||x||^2, strictly sequential fp32 (reference rounding order)
// ---------------------------------------------------------------------------
__global__ void __launch_bounds__(256) srow_kernel(const float* __restrict__ x) {
    int r = blockIdx.x * blockDim.x + threadIdx.x;
    if (r >= NROWS) return;
    const float4* row = (const float4*)(x + (size_t)r * D);
    float s = 0.0f;
#pragma unroll
    for (int q = 0; q < D / 4; q++) {
        float4 v = row[q];
        s = __fadd_rn(s, __fmul_rn(v.x, v.x));
        s = __fadd_rn(s, __fmul_rn(v.y, v.y));
        s = __fadd_rn(s, __fmul_rn(v.z, v.z));
        s = __fadd_rn(s, __fmul_rn(v.w, v.w));
    }
    g_srow[r] = s;
}

// ---------------------------------------------------------------------------
// K1: cnorm (sequential fp32) + codebook copy + bf16 codebook + hist init
// ---------------------------------------------------------------------------
__global__ void __launch_bounds__(256) prep_kernel(const float* __restrict__ cb,
                                                   float* __restrict__ outcb) {
    int gid = blockIdx.x * blockDim.x + threadIdx.x;   // 0..65535
    if (gid < NC) g_hist[gid] = 0;

    int wid  = gid >> 5;
    int lane = gid & 31;
    const float* row  = cb    + (size_t)wid * D;
    float*       orow = outcb + (size_t)wid * D;
#pragma unroll
    for (int j = 0; j < 8; j++) orow[lane + 32 * j] = row[lane + 32 * j];

    if (gid < NC) {
        const float4* crow = (const float4*)(cb + (size_t)gid * D);
        float s = 0.0f;
#pragma unroll
        for (int q = 0; q < D / 4; q++) {
            float4 v = crow[q];
            s = __fadd_rn(s, __fmul_rn(v.x, v.x));
            s = __fadd_rn(s, __fmul_rn(v.y, v.y));
            s = __fadd_rn(s, __fmul_rn(v.z, v.z));
            s = __fadd_rn(s, __fmul_rn(v.w, v.w));
        }
        g_cnorm[gid] = s;
    }

    // bf16 codebook: 8 floats/thread
    {
        const float4* src = (const float4*)cb;
        float4 v0 = src[gid * 2], v1 = src[gid * 2 + 1];
        __nv_bfloat16 b[8];
        b[0] = __float2bfloat16(v0.x); b[1] = __float2bfloat16(v0.y);
        b[2] = __float2bfloat16(v0.z); b[3] = __float2bfloat16(v0.w);
        b[4] = __float2bfloat16(v1.x); b[5] = __float2bfloat16(v1.y);
        b[6] = __float2bfloat16(v1.z); b[7] = __float2bfloat16(v1.w);
        ((uint4*)g_cb)[gid] = *(uint4*)b;
    }
}

// cp.async one 32-centroid bf16 chunk into smem (row stride 528B)
__device__ __forceinline__ void stage_c(uint32_t dst, int cbase, int tid) {
    const char* src = (const char*)(g_cb + (size_t)cbase * D);
#pragma unroll
    for (int i = 0; i < 4; i++) {
        int idx = tid + i * 256;              // 0..1023
        int r = idx >> 5, kp = (idx & 31) * 16;
        uint32_t d = dst + (uint32_t)(r * 528 + kp);
        const char* s = src + r * 512 + kp;
        asm volatile("cp.async.ca.shared.global [%0], [%1], 16;" :: "r"(d), "l"(s));
    }
}

// ---------------------------------------------------------------------------
// K2: HMMA bf16 approx GEMM + fused per-row top-4. 2 CTAs/SM.
// CTA: 128 rows x 2048 centroids. Warp w owns rows [w*16, w*16+16).
// ---------------------------------------------------------------------------
__global__ void __launch_bounds__(256, 2) approx_kernel(const float* __restrict__ x) {
    extern __shared__ char sm[];
    float* cn_sm = (float*)(sm + SM_CN);
    const int tid  = threadIdx.x;
    const int lane = tid & 31;
    const int w    = tid >> 5;
    const int rowBase = blockIdx.x * BM;
    const uint32_t smb = smem_u32(sm);
    const uint32_t xb  = smb + SM_X;
    const uint32_t cbA0 = smb + SM_C0, cbA1 = smb + SM_C1;

    for (int i = tid; i < NC; i += 256) cn_sm[i] = g_cnorm[i];

    // stage X (fp32 -> bf16) into x_sm
#pragma unroll
    for (int i = 0; i < 16; i++) {
        int idx = tid + i * 256;
        int r = idx >> 5, kp = (idx & 31) * 8;
        const float4* src = (const float4*)(x + (size_t)(rowBase + r) * D + kp);
        float4 v0 = src[0], v1 = src[1];
        __nv_bfloat16 b[8];
        b[0] = __float2bfloat16(v0.x); b[1] = __float2bfloat16(v0.y);
        b[2] = __float2bfloat16(v0.z); b[3] = __float2bfloat16(v0.w);
        b[4] = __float2bfloat16(v1.x); b[5] = __float2bfloat16(v1.y);
        b[6] = __float2bfloat16(v1.z); b[7] = __float2bfloat16(v1.w);
        *(uint4*)(sm + SM_X + r * 528 + kp * 2) = *(uint4*)b;
    }
    stage_c(cbA0, 0, tid);
    asm volatile("cp.async.commit_group;" ::: "memory");
    __syncthreads();

    // A fragments held in regs: 16 k-blocks (m16k16 each)
    uint32_t a[16][4];
#pragma unroll
    for (int kb = 0; kb < 16; kb++) {
        uint32_t addr = xb + (uint32_t)((w * 16 + (lane & 15)) * 528
                                        + (kb * 16 + (lane >> 4) * 8) * 2);
        asm volatile("ldmatrix.sync.aligned.m8n8.x4.shared.b16 {%0,%1,%2,%3}, [%4];"
                     : "=r"(a[kb][0]), "=r"(a[kb][1]), "=r"(a[kb][2]), "=r"(a[kb][3])
                     : "r"(addr));
    }

    unsigned long long top[2][4];
#pragma unroll
    for (int h = 0; h < 2; h++)
#pragma unroll
        for (int j = 0; j < 4; j++) top[h][j] = 0xFFFFFFFFFFFFFFFFULL;

    for (int ch = 0; ch < NCHUNK; ch++) {
        if (ch + 1 < NCHUNK) {
            stage_c(((ch + 1) & 1) ? cbA1 : cbA0, (ch + 1) * CHUNK, tid);
            asm volatile("cp.async.commit_group;" ::: "memory");
            asm volatile("cp.async.wait_group 1;" ::: "memory");
        } else {
            asm volatile("cp.async.wait_group 0;" ::: "memory");
        }
        __syncthreads();

        const uint32_t cbB = (ch & 1) ? cbA1 : cbA0;
        float acc[4][4];
#pragma unroll
        for (int nt = 0; nt < 4; nt++)
#pragma unroll
            for (int e = 0; e < 4; e++) acc[nt][e] = 0.0f;

#pragma unroll
        for (int kb = 0; kb < 16; kb++) {
#pragma unroll
            for (int np = 0; np < 2; np++) {
                uint32_t addr = cbB + (uint32_t)((np * 16 + (lane & 7) + (lane >> 4) * 8) * 528
                                                 + (kb * 16 + ((lane >> 3) & 1) * 8) * 2);
                uint32_t b0, b1, b2, b3;
                asm volatile("ldmatrix.sync.aligned.m8n8.x4.shared.b16 {%0,%1,%2,%3}, [%4];"
                             : "=r"(b0), "=r"(b1), "=r"(b2), "=r"(b3) : "r"(addr));
                asm volatile("mma.sync.aligned.m16n8k16.row.col.f32.bf16.bf16.f32 "
                             "{%0,%1,%2,%3}, {%4,%5,%6,%7}, {%8,%9}, {%0,%1,%2,%3};"
                             : "+f"(acc[np*2][0]), "+f"(acc[np*2][1]),
                               "+f"(acc[np*2][2]), "+f"(acc[np*2][3])
                             : "r"(a[kb][0]), "r"(a[kb][1]), "r"(a[kb][2]), "r"(a[kb][3]),
                               "r"(b0), "r"(b1));
                asm volatile("mma.sync.aligned.m16n8k16.row.col.f32.bf16.bf16.f32 "
                             "{%0,%1,%2,%3}, {%4,%5,%6,%7}, {%8,%9}, {%0,%1,%2,%3};"
                             : "+f"(acc[np*2+1][0]), "+f"(acc[np*2+1][1]),
                               "+f"(acc[np*2+1][2]), "+f"(acc[np*2+1][3])
                             : "r"(a[kb][0]), "r"(a[kb][1]), "r"(a[kb][2]), "r"(a[kb][3]),
                               "r"(b2), "r"(b3));
            }
        }

        // epilogue: approx score = cn - 2d ; per-thread top-4
        int kbase = ch * CHUNK + (lane & 3) * 2;
#pragma unroll
        for (int nt = 0; nt < 4; nt++) {
#pragma unroll
            for (int e = 0; e < 4; e++) {
                int k = kbase + nt * 8 + (e & 1);
                float sc = __fmaf_rn(-2.0f, acc[nt][e], cn_sm[k]);
                uint32_t bb = __float_as_uint(sc);
                uint32_t key = (bb & 0x80000000u) ? ~bb : (bb | 0x80000000u);
                unsigned long long u = ((unsigned long long)key << 32) | (uint32_t)k;
                insert4(top[e >> 1], u);
            }
        }
        __syncthreads();
    }

    // merge top-4 across the 4 lanes sharing each row, write candidates
#pragma unroll
    for (int h = 0; h < 2; h++) {
        unsigned long long v0 = top[h][0], v1 = top[h][1], v2 = top[h][2], v3 = top[h][3];
#pragma unroll
        for (int m = 1; m <= 2; m <<= 1) {
            unsigned long long o0 = __shfl_xor_sync(0xFFFFFFFFu, v0, m);
            unsigned long long o1 = __shfl_xor_sync(0xFFFFFFFFu, v1, m);
            unsigned long long o2 = __shfl_xor_sync(0xFFFFFFFFu, v2, m);
            unsigned long long o3 = __shfl_xor_sync(0xFFFFFFFFu, v3, m);
            unsigned long long s0 = v0 < o3 ? v0 : o3;
            unsigned long long s1 = v1 < o2 ? v1 : o2;
            unsigned long long s2 = v2 < o1 ? v2 : o1;
            unsigned long long s3 = v3 < o0 ? v3 : o0;
            unsigned long long a0 = s0 < s2 ? s0 : s2, a2 = s0 < s2 ? s2 : s0;
            unsigned long long a1 = s1 < s3 ? s1 : s3, a3 = s1 < s3 ? s3 : s1;
            v0 = a0 < a1 ? a0 : a1; v1 = a0 < a1 ? a1 : a0;
            v2 = a2 < a3 ? a2 : a3; v3 = a2 < a3 ? a3 : a2;
        }
        if ((lane & 3) == 0) {
            int row = rowBase + w * 16 + (lane >> 2) + h * 8;
            uint4 st;
            st.x = (uint32_t)v0; st.y = (uint32_t)v1;
            st.z = (uint32_t)v2; st.w = (uint32_t)v3;
            *(uint4*)&g_cand[row * 4] = st;
        }
    }
}

// ---------------------------------------------------------------------------
// K3: fused exact rescore + gather + loss + hist. warp = row.
// lane = (cand group c = lane>>3, seg s = lane&7). Element layout: float4
// index q*8+s (q outer) -> per LDG.128: x = 1 line (broadcast across groups),
// cands = 4 lines. 8x fewer L1 wavefronts than the R5 layout.
// Winner group writes quantized + loss from registers/L1-hot x.
// ---------------------------------------------------------------------------
__global__ void __launch_bounds__(256) rescore_gather_kernel(const float* __restrict__ x,
                                                             const float* __restrict__ cb,
                                                             float* __restrict__ outq,
                                                             float* __restrict__ outl,
                                                             float* __restrict__ outnn) {
    int row  = (blockIdx.x * blockDim.x + threadIdx.x) >> 5;
    int lane = threadIdx.x & 31;
    if (row >= NROWS) return;
    int c = lane >> 3, s = lane & 7;

    unsigned int cand = g_cand[row * 4 + c];
    const float4* c4 = (const float4*)(cb + (size_t)cand * D);
    const float4* x4 = (const float4*)(x + (size_t)row * D);

    float4 cv[8];
    float d = 0.0f;
#pragma unroll
    for (int q = 0; q < 8; q++) {
        float4 cq = c4[q * 8 + s];
        float4 xq = x4[q * 8 + s];
        cv[q] = cq;
        d = __fmaf_rn(xq.x, cq.x, d);
        d = __fmaf_rn(xq.y, cq.y, d);
        d = __fmaf_rn(xq.z, cq.z, d);
        d = __fmaf_rn(xq.w, cq.w, d);
    }
    // fixed-order tree within the 8-lane group
    d = __fadd_rn(d, __shfl_xor_sync(0xFFFFFFFFu, d, 1));
    d = __fadd_rn(d, __shfl_xor_sync(0xFFFFFFFFu, d, 2));
    d = __fadd_rn(d, __shfl_xor_sync(0xFFFFFFFFu, d, 4));

    float sc = __fadd_rn(__fmaf_rn(-2.0f, d, g_srow[row]), g_cnorm[cand]);
    uint32_t bb  = __float_as_uint(sc);
    uint32_t key = (bb & 0x80000000u) ? ~bb : (bb | 0x80000000u);
    unsigned long long best = ((unsigned long long)key << 32) | cand;

    unsigned long long o;
    o = __shfl_xor_sync(0xFFFFFFFFu, best, 8);  best = o < best ? o : best;
    o = __shfl_xor_sync(0xFFFFFFFFu, best, 16); best = o < best ? o : best;
    unsigned int wc = (unsigned int)best;

    if (lane == 0) {
        atomicAdd(&g_hist[wc], 1);
        outnn[row] = (float)wc;
    }

    if (cand == wc) {   // exactly one group (candidates are distinct)
        float4* qr = (float4*)(outq + (size_t)row * D);
        float4* lr = (float4*)(outl + (size_t)row * D);
#pragma unroll
        for (int q = 0; q < 8; q++) {
            float4 cq = cv[q];
            float4 xq = x4[q * 8 + s];   // L1 hit (just loaded above)
            qr[q * 8 + s] = cq;
            float4 L;
            L.x = 1.25f * (cq.x - xq.x) * (cq.x - xq.x);
            L.y = 1.25f * (cq.y - xq.y) * (cq.y - xq.y);
            L.z = 1.25f * (cq.z - xq.z) * (cq.z - xq.z);
            L.w = 1.25f * (cq.w - xq.w) * (cq.w - xq.w);
            lr[q * 8 + s] = L;
        }
    }
}

// K4: EMA counts
__global__ void counts_kernel(const float* __restrict__ cc, float* __restrict__ outc) {
    int k = blockIdx.x * blockDim.x + threadIdx.x;
    if (k < NC) outc[k] = 0.99f * cc[k] + 0.01f * (float)g_hist[k];
}

// ---------------------------------------------------------------------------
extern "C" void kernel_launch(void* const* d_in, const int* in_sizes, int n_in,
                              void* d_out, int out_size) {
    const float* x  = (const float*)d_in[0];
    const float* cb = (const float*)d_in[1];
    const float* cc = (const float*)d_in[2];
    float* out = (float*)d_out;

    cudaFuncSetAttribute(approx_kernel,
                         cudaFuncAttributeMaxDynamicSharedMemorySize, SM_TOTAL);

    srow_kernel<<<NROWS / 256, 256>>>(x);
    prep_kernel<<<256, 256>>>(cb, out + OFF_CB);
    approx_kernel<<<NROWS / BM, 256, SM_TOTAL>>>(x);
    rescore_gather_kernel<<<NROWS * 32 / 256, 256>>>(x, cb, out + OFF_Q, out + OFF_L, out + OFF_NN);
    counts_kernel<<<(NC + 255) / 256, 256>>>(cc, out + OFF_CNT);
}

// round 7
// speedup vs baseline: 4.1713x; 1.0808x over previous
#include <cuda_runtime.h>
#include <cuda_bf16.h>
#include <cstdint>

#define NC     2048
#define D      256
#define NROWS  32768
#define BM     128          // rows per CTA in approx kernel
#define CHUNK  64           // centroids per chunk
#define NCHUNK (NC / CHUNK) // 32
#define RING   3
#define SLOTSZ (CHUNK * 528)   // 33792 B per ring slot

// Output layout (float32):
#define OFF_Q    0
#define OFF_L    8388608
#define OFF_NN   16777216
#define OFF_CB   16809984
#define OFF_CNT  17334272

// SMEM map (bytes): ring (X staged here transiently) then cn.
#define SM_RING  0
#define SM_CN    (RING * SLOTSZ)          // 101376
#define SM_TOTAL (SM_CN + NC * 4)         // 109568  -> 2 CTAs/SM

// scratch (allocation-free)
__device__ float          g_cnorm[NC];
__device__ float          g_srow[NROWS];
__device__ __nv_bfloat16  g_cb[NC * D];
__device__ unsigned int   g_cand[NROWS * 4];
__device__ int            g_hist[NC];

__device__ __forceinline__ uint32_t smem_u32(const void* p) {
    uint32_t a;
    asm("{ .reg .u64 t; cvta.to.shared.u64 t, %1; cvt.u32.u64 %0, t; }" : "=r"(a) : "l"(p));
    return a;
}

__device__ __forceinline__ void insert4(unsigned long long* t, unsigned long long u) {
    if (u < t[3]) {
        if (u < t[2]) {
            t[3] = t[2];
            if (u < t[1]) {
                t[2] = t[1];
                if (u < t[0]) { t[1] = t[0]; t[0] = u; } else t[1] = u;
            } else t[2] = u;
        } else t[3] = u;
    }
}

// ---------------------------------------------------------------------------
// K0: merged init. blocks [0,128): per-row ||x||^2 sequential fp32.
// blocks [128,384): cnorm + codebook copy + bf16 codebook + hist init.
// ---------------------------------------------------------------------------
__global__ void __launch_bounds__(256) init_kernel(const float* __restrict__ x,
                                                   const float* __restrict__ cb,
                                                   float* __restrict__ outcb) {
    int b = blockIdx.x;
    if (b < 128) {
        int r = b * 256 + threadIdx.x;
        const float4* row = (const float4*)(x + (size_t)r * D);
        float s = 0.0f;
#pragma unroll
        for (int q = 0; q < D / 4; q++) {
            float4 v = row[q];
            s = __fadd_rn(s, __fmul_rn(v.x, v.x));
            s = __fadd_rn(s, __fmul_rn(v.y, v.y));
            s = __fadd_rn(s, __fmul_rn(v.z, v.z));
            s = __fadd_rn(s, __fmul_rn(v.w, v.w));
        }
        g_srow[r] = s;
        return;
    }
    int gid = (b - 128) * 256 + threadIdx.x;   // 0..65535
    if (gid < NC) g_hist[gid] = 0;

    int wid  = gid >> 5;
    int lane = gid & 31;
    const float* row  = cb    + (size_t)wid * D;
    float*       orow = outcb + (size_t)wid * D;
#pragma unroll
    for (int j = 0; j < 8; j++) orow[lane + 32 * j] = row[lane + 32 * j];

    if (gid < NC) {
        const float4* crow = (const float4*)(cb + (size_t)gid * D);
        float s = 0.0f;
#pragma unroll
        for (int q = 0; q < D / 4; q++) {
            float4 v = crow[q];
            s = __fadd_rn(s, __fmul_rn(v.x, v.x));
            s = __fadd_rn(s, __fmul_rn(v.y, v.y));
            s = __fadd_rn(s, __fmul_rn(v.z, v.z));
            s = __fadd_rn(s, __fmul_rn(v.w, v.w));
        }
        g_cnorm[gid] = s;
    }

    // bf16 codebook: 8 floats/thread
    {
        const float4* src = (const float4*)cb;
        float4 v0 = src[gid * 2], v1 = src[gid * 2 + 1];
        __nv_bfloat16 bb[8];
        bb[0] = __float2bfloat16(v0.x); bb[1] = __float2bfloat16(v0.y);
        bb[2] = __float2bfloat16(v0.z); bb[3] = __float2bfloat16(v0.w);
        bb[4] = __float2bfloat16(v1.x); bb[5] = __float2bfloat16(v1.y);
        bb[6] = __float2bfloat16(v1.z); bb[7] = __float2bfloat16(v1.w);
        ((uint4*)g_cb)[gid] = *(uint4*)bb;
    }
}

// cp.async one 64-centroid bf16 chunk into a ring slot (row stride 528B)
__device__ __forceinline__ void stage_c(uint32_t dst, int cbase, int tid) {
    const char* src = (const char*)(g_cb + (size_t)cbase * D);
#pragma unroll
    for (int i = 0; i < 8; i++) {
        int idx = tid + i * 256;              // 0..2047
        int r = idx >> 5, kp = (idx & 31) * 16;
        uint32_t d = dst + (uint32_t)(r * 528 + kp);
        const char* s = src + r * 512 + kp;
        asm volatile("cp.async.ca.shared.global [%0], [%1], 16;" :: "r"(d), "l"(s));
    }
}

// ---------------------------------------------------------------------------
// K2: HMMA bf16 approx GEMM + fused per-row top-4. 2 CTAs/SM.
// CTA: 128 rows x 2048 centroids. Warp w owns rows [w*16, w*16+16).
// 3-slot cp.async ring (aliased over the X staging area), 1 sync per chunk.
// ---------------------------------------------------------------------------
__global__ void __launch_bounds__(256, 2) approx_kernel(const float* __restrict__ x) {
    extern __shared__ char sm[];
    float* cn_sm = (float*)(sm + SM_CN);
    const int tid  = threadIdx.x;
    const int lane = tid & 31;
    const int w    = tid >> 5;
    const int rowBase = blockIdx.x * BM;
    const uint32_t smb = smem_u32(sm);

    for (int i = tid; i < NC; i += 256) cn_sm[i] = g_cnorm[i];

    // stage X (fp32 -> bf16) into ring region transiently (128 * 528 B)
#pragma unroll
    for (int i = 0; i < 16; i++) {
        int idx = tid + i * 256;
        int r = idx >> 5, kp = (idx & 31) * 8;
        const float4* src = (const float4*)(x + (size_t)(rowBase + r) * D + kp);
        float4 v0 = src[0], v1 = src[1];
        __nv_bfloat16 bb[8];
        bb[0] = __float2bfloat16(v0.x); bb[1] = __float2bfloat16(v0.y);
        bb[2] = __float2bfloat16(v0.z); bb[3] = __float2bfloat16(v0.w);
        bb[4] = __float2bfloat16(v1.x); bb[5] = __float2bfloat16(v1.y);
        bb[6] = __float2bfloat16(v1.z); bb[7] = __float2bfloat16(v1.w);
        *(uint4*)(sm + r * 528 + kp * 2) = *(uint4*)bb;
    }
    __syncthreads();

    // A fragments held in regs: 16 k-blocks (m16k16 each), read from X staging
    uint32_t a[16][4];
#pragma unroll
    for (int kb = 0; kb < 16; kb++) {
        uint32_t addr = smb + (uint32_t)((w * 16 + (lane & 15)) * 528
                                         + (kb * 16 + (lane >> 4) * 8) * 2);
        asm volatile("ldmatrix.sync.aligned.m8n8.x4.shared.b16 {%0,%1,%2,%3}, [%4];"
                     : "=r"(a[kb][0]), "=r"(a[kb][1]), "=r"(a[kb][2]), "=r"(a[kb][3])
                     : "r"(addr));
    }
    __syncthreads();   // X region now dead; becomes the C ring

    // prologue: stage chunks 0 and 1 into slots 0 and 1
    stage_c(smb + SM_RING + 0 * SLOTSZ, 0 * CHUNK, tid);
    asm volatile("cp.async.commit_group;" ::: "memory");
    stage_c(smb + SM_RING + 1 * SLOTSZ, 1 * CHUNK, tid);
    asm volatile("cp.async.commit_group;" ::: "memory");

    unsigned long long top[2][4];
#pragma unroll
    for (int h = 0; h < 2; h++)
#pragma unroll
        for (int j = 0; j < 4; j++) top[h][j] = 0xFFFFFFFFFFFFFFFFULL;

    int slot = 0;
    for (int ch = 0; ch < NCHUNK; ch++) {
        asm volatile("cp.async.wait_group 1;" ::: "memory");
        __syncthreads();   // slot `slot` (chunk ch) visible to all warps

        const uint32_t cbB = smb + (uint32_t)(SM_RING + slot * SLOTSZ);

        // process two 32-centroid halves to keep acc at 16 regs
#pragma unroll
        for (int half = 0; half < 2; half++) {
            float acc[4][4];
#pragma unroll
            for (int nt = 0; nt < 4; nt++)
#pragma unroll
                for (int e = 0; e < 4; e++) acc[nt][e] = 0.0f;

#pragma unroll
            for (int kb = 0; kb < 16; kb++) {
#pragma unroll
                for (int np = 0; np < 2; np++) {
                    uint32_t addr = cbB + (uint32_t)((half * 32 + np * 16
                                                      + (lane & 7) + (lane >> 4) * 8) * 528
                                                     + (kb * 16 + ((lane >> 3) & 1) * 8) * 2);
                    uint32_t b0, b1, b2, b3;
                    asm volatile("ldmatrix.sync.aligned.m8n8.x4.shared.b16 {%0,%1,%2,%3}, [%4];"
                                 : "=r"(b0), "=r"(b1), "=r"(b2), "=r"(b3) : "r"(addr));
                    asm volatile("mma.sync.aligned.m16n8k16.row.col.f32.bf16.bf16.f32 "
                                 "{%0,%1,%2,%3}, {%4,%5,%6,%7}, {%8,%9}, {%0,%1,%2,%3};"
                                 : "+f"(acc[np*2][0]), "+f"(acc[np*2][1]),
                                   "+f"(acc[np*2][2]), "+f"(acc[np*2][3])
                                 : "r"(a[kb][0]), "r"(a[kb][1]), "r"(a[kb][2]), "r"(a[kb][3]),
                                   "r"(b0), "r"(b1));
                    asm volatile("mma.sync.aligned.m16n8k16.row.col.f32.bf16.bf16.f32 "
                                 "{%0,%1,%2,%3}, {%4,%5,%6,%7}, {%8,%9}, {%0,%1,%2,%3};"
                                 : "+f"(acc[np*2+1][0]), "+f"(acc[np*2+1][1]),
                                   "+f"(acc[np*2+1][2]), "+f"(acc[np*2+1][3])
                                 : "r"(a[kb][0]), "r"(a[kb][1]), "r"(a[kb][2]), "r"(a[kb][3]),
                                   "r"(b2), "r"(b3));
                }
            }

            // epilogue: approx score = cn - 2d ; per-thread top-4
            int kbase = ch * CHUNK + half * 32 + (lane & 3) * 2;
#pragma unroll
            for (int nt = 0; nt < 4; nt++) {
#pragma unroll
                for (int e = 0; e < 4; e++) {
                    int k = kbase + nt * 8 + (e & 1);
                    float sc = __fmaf_rn(-2.0f, acc[nt][e], cn_sm[k]);
                    uint32_t bb = __float_as_uint(sc);
                    uint32_t key = (bb & 0x80000000u) ? ~bb : (bb | 0x80000000u);
                    unsigned long long u = ((unsigned long long)key << 32) | (uint32_t)k;
                    insert4(top[e >> 1], u);
                }
            }
        }

        // stage chunk ch+2 into the slot consumed at iter ch-1 (safe: sync above)
        if (ch + 2 < NCHUNK) {
            int ns = slot + 2; if (ns >= RING) ns -= RING;
            stage_c(smb + (uint32_t)(SM_RING + ns * SLOTSZ), (ch + 2) * CHUNK, tid);
        }
        asm volatile("cp.async.commit_group;" ::: "memory");  // one group per iter
        slot = (slot + 1 == RING) ? 0 : slot + 1;
    }

    // merge top-4 across the 4 lanes sharing each row, write candidates
#pragma unroll
    for (int h = 0; h < 2; h++) {
        unsigned long long v0 = top[h][0], v1 = top[h][1], v2 = top[h][2], v3 = top[h][3];
#pragma unroll
        for (int m = 1; m <= 2; m <<= 1) {
            unsigned long long o0 = __shfl_xor_sync(0xFFFFFFFFu, v0, m);
            unsigned long long o1 = __shfl_xor_sync(0xFFFFFFFFu, v1, m);
            unsigned long long o2 = __shfl_xor_sync(0xFFFFFFFFu, v2, m);
            unsigned long long o3 = __shfl_xor_sync(0xFFFFFFFFu, v3, m);
            unsigned long long s0 = v0 < o3 ? v0 : o3;
            unsigned long long s1 = v1 < o2 ? v1 : o2;
            unsigned long long s2 = v2 < o1 ? v2 : o1;
            unsigned long long s3 = v3 < o0 ? v3 : o0;
            unsigned long long a0 = s0 < s2 ? s0 : s2, a2 = s0 < s2 ? s2 : s0;
            unsigned long long a1 = s1 < s3 ? s1 : s3, a3 = s1 < s3 ? s3 : s1;
            v0 = a0 < a1 ? a0 : a1; v1 = a0 < a1 ? a1 : a0;
            v2 = a2 < a3 ? a2 : a3; v3 = a2 < a3 ? a3 : a2;
        }
        if ((lane & 3) == 0) {
            int row = rowBase + w * 16 + (lane >> 2) + h * 8;
            uint4 st;
            st.x = (uint32_t)v0; st.y = (uint32_t)v1;
            st.z = (uint32_t)v2; st.w = (uint32_t)v3;
            *(uint4*)&g_cand[row * 4] = st;
        }
    }
}

// ---------------------------------------------------------------------------
// K3: fused exact rescore + gather + loss + hist. warp = row.
// lane = (cand group c = lane>>3, seg s = lane&7); element float4 q*8+s.
// cv not kept in regs: winner group reloads cb/x from L1 in the write phase.
// ---------------------------------------------------------------------------
__global__ void __launch_bounds__(256) rescore_gather_kernel(const float* __restrict__ x,
                                                             const float* __restrict__ cb,
                                                             float* __restrict__ outq,
                                                             float* __restrict__ outl,
                                                             float* __restrict__ outnn) {
    int row  = (blockIdx.x * blockDim.x + threadIdx.x) >> 5;
    int lane = threadIdx.x & 31;
    if (row >= NROWS) return;
    int c = lane >> 3, s = lane & 7;

    unsigned int cand = g_cand[row * 4 + c];
    const float4* c4 = (const float4*)(cb + (size_t)cand * D);
    const float4* x4 = (const float4*)(x + (size_t)row * D);

    float d = 0.0f;
#pragma unroll
    for (int q = 0; q < 8; q++) {
        float4 cq = c4[q * 8 + s];
        float4 xq = x4[q * 8 + s];
        d = __fmaf_rn(xq.x, cq.x, d);
        d = __fmaf_rn(xq.y, cq.y, d);
        d = __fmaf_rn(xq.z, cq.z, d);
        d = __fmaf_rn(xq.w, cq.w, d);
    }
    d = __fadd_rn(d, __shfl_xor_sync(0xFFFFFFFFu, d, 1));
    d = __fadd_rn(d, __shfl_xor_sync(0xFFFFFFFFu, d, 2));
    d = __fadd_rn(d, __shfl_xor_sync(0xFFFFFFFFu, d, 4));

    float sc = __fadd_rn(__fmaf_rn(-2.0f, d, g_srow[row]), g_cnorm[cand]);
    uint32_t bb  = __float_as_uint(sc);
    uint32_t key = (bb & 0x80000000u) ? ~bb : (bb | 0x80000000u);
    unsigned long long best = ((unsigned long long)key << 32) | cand;

    unsigned long long o;
    o = __shfl_xor_sync(0xFFFFFFFFu, best, 8);  best = o < best ? o : best;
    o = __shfl_xor_sync(0xFFFFFFFFu, best, 16); best = o < best ? o : best;
    unsigned int wc = (unsigned int)best;

    if (lane == 0) {
        atomicAdd(&g_hist[wc], 1);
        outnn[row] = (float)wc;
    }

    if (cand == wc) {   // exactly one group (candidates are distinct)
        float4* qr = (float4*)(outq + (size_t)row * D);
        float4* lr = (float4*)(outl + (size_t)row * D);
#pragma unroll
        for (int q = 0; q < 8; q++) {
            float4 cq = c4[q * 8 + s];   // L1 hit
            float4 xq = x4[q * 8 + s];   // L1 hit
            qr[q * 8 + s] = cq;
            float4 L;
            L.x = 1.25f * (cq.x - xq.x) * (cq.x - xq.x);
            L.y = 1.25f * (cq.y - xq.y) * (cq.y - xq.y);
            L.z = 1.25f * (cq.z - xq.z) * (cq.z - xq.z);
            L.w = 1.25f * (cq.w - xq.w) * (cq.w - xq.w);
            lr[q * 8 + s] = L;
        }
    }
}

// K4: EMA counts
__global__ void counts_kernel(const float* __restrict__ cc, float* __restrict__ outc) {
    int k = blockIdx.x * blockDim.x + threadIdx.x;
    if (k < NC) outc[k] = 0.99f * cc[k] + 0.01f * (float)g_hist[k];
}

// ---------------------------------------------------------------------------
extern "C" void kernel_launch(void* const* d_in, const int* in_sizes, int n_in,
                              void* d_out, int out_size) {
    const float* x  = (const float*)d_in[0];
    const float* cb = (const float*)d_in[1];
    const float* cc = (const float*)d_in[2];
    float* out = (float*)d_out;

    cudaFuncSetAttribute(approx_kernel,
                         cudaFuncAttributeMaxDynamicSharedMemorySize, SM_TOTAL);

    init_kernel<<<384, 256>>>(x, cb, out + OFF_CB);
    approx_kernel<<<NROWS / BM, 256, SM_TOTAL>>>(x);
    rescore_gather_kernel<<<NROWS * 32 / 256, 256>>>(x, cb, out + OFF_Q, out + OFF_L, out + OFF_NN);
    counts_kernel<<<(NC + 255) / 256, 256>>>(cc, out + OFF_CNT);
}

// round 8
// speedup vs baseline: 4.2214x; 1.0120x over previous
#include <cuda_runtime.h>
#include <cuda_bf16.h>
#include <cstdint>

#define NC     2048
#define D      256
#define NROWS  32768
#define BM     128          // rows per CTA in approx kernel
#define CHUNK  64           // centroids per chunk
#define NCHUNK (NC / CHUNK) // 32
#define RING   3
#define SLOTSZ (CHUNK * 528)   // 33792 B per ring slot

// Output layout (float32):
#define OFF_Q    0
#define OFF_L    8388608
#define OFF_NN   16777216
#define OFF_CB   16809984
#define OFF_CNT  17334272

// SMEM map (bytes): ring (X staged here transiently) then cn.
#define SM_RING  0
#define SM_CN    (RING * SLOTSZ)          // 101376
#define SM_TOTAL (SM_CN + NC * 4)         // 109568  -> 2 CTAs/SM

// scratch (allocation-free)
__device__ float          g_cnorm[NC];
__device__ float          g_srow[NROWS];
__device__ __nv_bfloat16  g_cb[NC * D];
__device__ unsigned int   g_cand[NROWS * 4];
__device__ int            g_hist[NC];

__device__ __forceinline__ uint32_t smem_u32(const void* p) {
    uint32_t a;
    asm("{ .reg .u64 t; cvta.to.shared.u64 t, %1; cvt.u32.u64 %0, t; }" : "=r"(a) : "l"(p));
    return a;
}

__device__ __forceinline__ void insert4(unsigned long long* t, unsigned long long u) {
    if (u < t[3]) {
        if (u < t[2]) {
            t[3] = t[2];
            if (u < t[1]) {
                t[2] = t[1];
                if (u < t[0]) { t[1] = t[0]; t[0] = u; } else t[1] = u;
            } else t[2] = u;
        } else t[3] = u;
    }
}

// ---------------------------------------------------------------------------
// K0: merged init. blocks [0,128): per-row ||x||^2 sequential fp32.
// blocks [128,384): cnorm + codebook copy + bf16 codebook + hist init.
// ---------------------------------------------------------------------------
__global__ void __launch_bounds__(256) init_kernel(const float* __restrict__ x,
                                                   const float* __restrict__ cb,
                                                   float* __restrict__ outcb) {
    int b = blockIdx.x;
    if (b < 128) {
        int r = b * 256 + threadIdx.x;
        const float4* row = (const float4*)(x + (size_t)r * D);
        float s = 0.0f;
#pragma unroll
        for (int q = 0; q < D / 4; q++) {
            float4 v = row[q];
            s = __fadd_rn(s, __fmul_rn(v.x, v.x));
            s = __fadd_rn(s, __fmul_rn(v.y, v.y));
            s = __fadd_rn(s, __fmul_rn(v.z, v.z));
            s = __fadd_rn(s, __fmul_rn(v.w, v.w));
        }
        g_srow[r] = s;
        return;
    }
    int gid = (b - 128) * 256 + threadIdx.x;   // 0..65535
    if (gid < NC) g_hist[gid] = 0;

    int wid  = gid >> 5;
    int lane = gid & 31;
    const float* row  = cb    + (size_t)wid * D;
    float*       orow = outcb + (size_t)wid * D;
#pragma unroll
    for (int j = 0; j < 8; j++) orow[lane + 32 * j] = row[lane + 32 * j];

    if (gid < NC) {
        const float4* crow = (const float4*)(cb + (size_t)gid * D);
        float s = 0.0f;
#pragma unroll
        for (int q = 0; q < D / 4; q++) {
            float4 v = crow[q];
            s = __fadd_rn(s, __fmul_rn(v.x, v.x));
            s = __fadd_rn(s, __fmul_rn(v.y, v.y));
            s = __fadd_rn(s, __fmul_rn(v.z, v.z));
            s = __fadd_rn(s, __fmul_rn(v.w, v.w));
        }
        g_cnorm[gid] = s;
    }

    // bf16 codebook: 8 floats/thread
    {
        const float4* src = (const float4*)cb;
        float4 v0 = src[gid * 2], v1 = src[gid * 2 + 1];
        __nv_bfloat16 bb[8];
        bb[0] = __float2bfloat16(v0.x); bb[1] = __float2bfloat16(v0.y);
        bb[2] = __float2bfloat16(v0.z); bb[3] = __float2bfloat16(v0.w);
        bb[4] = __float2bfloat16(v1.x); bb[5] = __float2bfloat16(v1.y);
        bb[6] = __float2bfloat16(v1.z); bb[7] = __float2bfloat16(v1.w);
        ((uint4*)g_cb)[gid] = *(uint4*)bb;
    }
}

// cp.async one 64-centroid bf16 chunk into a ring slot (row stride 528B)
__device__ __forceinline__ void stage_c(uint32_t dst, int cbase, int tid) {
    const char* src = (const char*)(g_cb + (size_t)cbase * D);
#pragma unroll
    for (int i = 0; i < 8; i++) {
        int idx = tid + i * 256;              // 0..2047
        int r = idx >> 5, kp = (idx & 31) * 16;
        uint32_t d = dst + (uint32_t)(r * 528 + kp);
        const char* s = src + r * 512 + kp;
        asm volatile("cp.async.ca.shared.global [%0], [%1], 16;" :: "r"(d), "l"(s));
    }
}

// ---------------------------------------------------------------------------
// K2: HMMA bf16 approx GEMM + fused per-row top-4. 2 CTAs/SM.
// CTA: 128 rows x 2048 centroids. Warp w owns rows [w*16, w*16+16).
// 3-slot cp.async ring; B fragments software-pipelined (distance 2) so
// LDSM latency hides under the HMMA chain and both pipes stay busy.
// ---------------------------------------------------------------------------
__global__ void __launch_bounds__(256, 2) approx_kernel(const float* __restrict__ x) {
    extern __shared__ char sm[];
    float* cn_sm = (float*)(sm + SM_CN);
    const int tid  = threadIdx.x;
    const int lane = tid & 31;
    const int w    = tid >> 5;
    const int rowBase = blockIdx.x * BM;
    const uint32_t smb = smem_u32(sm);

    for (int i = tid; i < NC; i += 256) cn_sm[i] = g_cnorm[i];

    // stage X (fp32 -> bf16) into ring region transiently (128 * 528 B)
#pragma unroll
    for (int i = 0; i < 16; i++) {
        int idx = tid + i * 256;
        int r = idx >> 5, kp = (idx & 31) * 8;
        const float4* src = (const float4*)(x + (size_t)(rowBase + r) * D + kp);
        float4 v0 = src[0], v1 = src[1];
        __nv_bfloat16 bb[8];
        bb[0] = __float2bfloat16(v0.x); bb[1] = __float2bfloat16(v0.y);
        bb[2] = __float2bfloat16(v0.z); bb[3] = __float2bfloat16(v0.w);
        bb[4] = __float2bfloat16(v1.x); bb[5] = __float2bfloat16(v1.y);
        bb[6] = __float2bfloat16(v1.z); bb[7] = __float2bfloat16(v1.w);
        *(uint4*)(sm + r * 528 + kp * 2) = *(uint4*)bb;
    }
    __syncthreads();

    // A fragments held in regs: 16 k-blocks (m16k16 each), read from X staging
    uint32_t a[16][4];
#pragma unroll
    for (int kb = 0; kb < 16; kb++) {
        uint32_t addr = smb + (uint32_t)((w * 16 + (lane & 15)) * 528
                                         + (kb * 16 + (lane >> 4) * 8) * 2);
        asm volatile("ldmatrix.sync.aligned.m8n8.x4.shared.b16 {%0,%1,%2,%3}, [%4];"
                     : "=r"(a[kb][0]), "=r"(a[kb][1]), "=r"(a[kb][2]), "=r"(a[kb][3])
                     : "r"(addr));
    }
    __syncthreads();   // X region now dead; becomes the C ring

    // prologue: stage chunks 0 and 1 into slots 0 and 1
    stage_c(smb + SM_RING + 0 * SLOTSZ, 0 * CHUNK, tid);
    asm volatile("cp.async.commit_group;" ::: "memory");
    stage_c(smb + SM_RING + 1 * SLOTSZ, 1 * CHUNK, tid);
    asm volatile("cp.async.commit_group;" ::: "memory");

    unsigned long long top[2][4];
#pragma unroll
    for (int h = 0; h < 2; h++)
#pragma unroll
        for (int j = 0; j < 4; j++) top[h][j] = 0xFFFFFFFFFFFFFFFFULL;

    // per-lane base offsets for B ldmatrix addressing
    const uint32_t bRowOff = (uint32_t)(((lane & 7) + (lane >> 4) * 8) * 528
                                        + ((lane >> 3) & 1) * 16);

    int slot = 0;
    for (int ch = 0; ch < NCHUNK; ch++) {
        asm volatile("cp.async.wait_group 1;" ::: "memory");
        __syncthreads();   // slot `slot` (chunk ch) visible to all warps

        const uint32_t cbB = smb + (uint32_t)(SM_RING + slot * SLOTSZ) + bRowOff;

        // process two 32-centroid halves to keep acc at 16 regs
#pragma unroll
        for (int half = 0; half < 2; half++) {
            float acc[4][4];
#pragma unroll
            for (int nt = 0; nt < 4; nt++)
#pragma unroll
                for (int e = 0; e < 4; e++) acc[nt][e] = 0.0f;

            // flattened steps s = kb*2 + np; 2-slot B-frag ring, prefetch +2
            uint32_t bb[2][4];
#pragma unroll
            for (int p = 0; p < 2; p++) {
                uint32_t addr = cbB + (uint32_t)((half * 32 + p * 16) * 528);
                asm volatile("ldmatrix.sync.aligned.m8n8.x4.shared.b16 {%0,%1,%2,%3}, [%4];"
                             : "=r"(bb[p][0]), "=r"(bb[p][1]), "=r"(bb[p][2]), "=r"(bb[p][3])
                             : "r"(addr));
            }
#pragma unroll
            for (int s = 0; s < 32; s++) {
                const int kb = s >> 1, np = s & 1;
                asm volatile("mma.sync.aligned.m16n8k16.row.col.f32.bf16.bf16.f32 "
                             "{%0,%1,%2,%3}, {%4,%5,%6,%7}, {%8,%9}, {%0,%1,%2,%3};"
                             : "+f"(acc[np*2][0]), "+f"(acc[np*2][1]),
                               "+f"(acc[np*2][2]), "+f"(acc[np*2][3])
                             : "r"(a[kb][0]), "r"(a[kb][1]), "r"(a[kb][2]), "r"(a[kb][3]),
                               "r"(bb[s & 1][0]), "r"(bb[s & 1][1]));
                asm volatile("mma.sync.aligned.m16n8k16.row.col.f32.bf16.bf16.f32 "
                             "{%0,%1,%2,%3}, {%4,%5,%6,%7}, {%8,%9}, {%0,%1,%2,%3};"
                             : "+f"(acc[np*2+1][0]), "+f"(acc[np*2+1][1]),
                               "+f"(acc[np*2+1][2]), "+f"(acc[np*2+1][3])
                             : "r"(a[kb][0]), "r"(a[kb][1]), "r"(a[kb][2]), "r"(a[kb][3]),
                               "r"(bb[s & 1][2]), "r"(bb[s & 1][3]));
                if (s + 2 < 32) {
                    const int s2 = s + 2;
                    uint32_t addr = cbB + (uint32_t)((half * 32 + (s2 & 1) * 16) * 528
                                                     + ((s2 >> 1) * 16) * 2);
                    asm volatile("ldmatrix.sync.aligned.m8n8.x4.shared.b16 {%0,%1,%2,%3}, [%4];"
                                 : "=r"(bb[s & 1][0]), "=r"(bb[s & 1][1]),
                                   "=r"(bb[s & 1][2]), "=r"(bb[s & 1][3])
                                 : "r"(addr));
                }
            }

            // epilogue: approx score = cn - 2d ; per-thread top-4
            int kbase = ch * CHUNK + half * 32 + (lane & 3) * 2;
#pragma unroll
            for (int nt = 0; nt < 4; nt++) {
#pragma unroll
                for (int e = 0; e < 4; e++) {
                    int k = kbase + nt * 8 + (e & 1);
                    float sc = __fmaf_rn(-2.0f, acc[nt][e], cn_sm[k]);
                    uint32_t bv = __float_as_uint(sc);
                    uint32_t key = (bv & 0x80000000u) ? ~bv : (bv | 0x80000000u);
                    unsigned long long u = ((unsigned long long)key << 32) | (uint32_t)k;
                    insert4(top[e >> 1], u);
                }
            }
        }

        // stage chunk ch+2 into the slot consumed at iter ch-1 (safe: sync above)
        if (ch + 2 < NCHUNK) {
            int ns = slot + 2; if (ns >= RING) ns -= RING;
            stage_c(smb + (uint32_t)(SM_RING + ns * SLOTSZ), (ch + 2) * CHUNK, tid);
        }
        asm volatile("cp.async.commit_group;" ::: "memory");  // one group per iter
        slot = (slot + 1 == RING) ? 0 : slot + 1;
    }

    // merge top-4 across the 4 lanes sharing each row, write candidates
#pragma unroll
    for (int h = 0; h < 2; h++) {
        unsigned long long v0 = top[h][0], v1 = top[h][1], v2 = top[h][2], v3 = top[h][3];
#pragma unroll
        for (int m = 1; m <= 2; m <<= 1) {
            unsigned long long o0 = __shfl_xor_sync(0xFFFFFFFFu, v0, m);
            unsigned long long o1 = __shfl_xor_sync(0xFFFFFFFFu, v1, m);
            unsigned long long o2 = __shfl_xor_sync(0xFFFFFFFFu, v2, m);
            unsigned long long o3 = __shfl_xor_sync(0xFFFFFFFFu, v3, m);
            unsigned long long s0 = v0 < o3 ? v0 : o3;
            unsigned long long s1 = v1 < o2 ? v1 : o2;
            unsigned long long s2 = v2 < o1 ? v2 : o1;
            unsigned long long s3 = v3 < o0 ? v3 : o0;
            unsigned long long a0 = s0 < s2 ? s0 : s2, a2 = s0 < s2 ? s2 : s0;
            unsigned long long a1 = s1 < s3 ? s1 : s3, a3 = s1 < s3 ? s3 : s1;
            v0 = a0 < a1 ? a0 : a1; v1 = a0 < a1 ? a1 : a0;
            v2 = a2 < a3 ? a2 : a3; v3 = a2 < a3 ? a3 : a2;
        }
        if ((lane & 3) == 0) {
            int row = rowBase + w * 16 + (lane >> 2) + h * 8;
            uint4 st;
            st.x = (uint32_t)v0; st.y = (uint32_t)v1;
            st.z = (uint32_t)v2; st.w = (uint32_t)v3;
            *(uint4*)&g_cand[row * 4] = st;
        }
    }
}

// ---------------------------------------------------------------------------
// K3: fused exact rescore + gather + loss + hist. warp = row.
// lane = (cand group c = lane>>3, seg s = lane&7); element float4 q*8+s.
// ---------------------------------------------------------------------------
__global__ void __launch_bounds__(256) rescore_gather_kernel(const float* __restrict__ x,
                                                             const float* __restrict__ cb,
                                                             float* __restrict__ outq,
                                                             float* __restrict__ outl,
                                                             float* __restrict__ outnn) {
    int row  = (blockIdx.x * blockDim.x + threadIdx.x) >> 5;
    int lane = threadIdx.x & 31;
    if (row >= NROWS) return;
    int c = lane >> 3, s = lane & 7;

    unsigned int cand = g_cand[row * 4 + c];
    const float4* c4 = (const float4*)(cb + (size_t)cand * D);
    const float4* x4 = (const float4*)(x + (size_t)row * D);

    float d = 0.0f;
#pragma unroll
    for (int q = 0; q < 8; q++) {
        float4 cq = c4[q * 8 + s];
        float4 xq = x4[q * 8 + s];
        d = __fmaf_rn(xq.x, cq.x, d);
        d = __fmaf_rn(xq.y, cq.y, d);
        d = __fmaf_rn(xq.z, cq.z, d);
        d = __fmaf_rn(xq.w, cq.w, d);
    }
    d = __fadd_rn(d, __shfl_xor_sync(0xFFFFFFFFu, d, 1));
    d = __fadd_rn(d, __shfl_xor_sync(0xFFFFFFFFu, d, 2));
    d = __fadd_rn(d, __shfl_xor_sync(0xFFFFFFFFu, d, 4));

    float sc = __fadd_rn(__fmaf_rn(-2.0f, d, g_srow[row]), g_cnorm[cand]);
    uint32_t bb  = __float_as_uint(sc);
    uint32_t key = (bb & 0x80000000u) ? ~bb : (bb | 0x80000000u);
    unsigned long long best = ((unsigned long long)key << 32) | cand;

    unsigned long long o;
    o = __shfl_xor_sync(0xFFFFFFFFu, best, 8);  best = o < best ? o : best;
    o = __shfl_xor_sync(0xFFFFFFFFu, best, 16); best = o < best ? o : best;
    unsigned int wc = (unsigned int)best;

    if (lane == 0) {
        atomicAdd(&g_hist[wc], 1);
        outnn[row] = (float)wc;
    }

    if (cand == wc) {   // exactly one group (candidates are distinct)
        float4* qr = (float4*)(outq + (size_t)row * D);
        float4* lr = (float4*)(outl + (size_t)row * D);
#pragma unroll
        for (int q = 0; q < 8; q++) {
            float4 cq = c4[q * 8 + s];   // L1 hit
            float4 xq = x4[q * 8 + s];   // L1 hit
            qr[q * 8 + s] = cq;
            float4 L;
            L.x = 1.25f * (cq.x - xq.x) * (cq.x - xq.x);
            L.y = 1.25f * (cq.y - xq.y) * (cq.y - xq.y);
            L.z = 1.25f * (cq.z - xq.z) * (cq.z - xq.z);
            L.w = 1.25f * (cq.w - xq.w) * (cq.w - xq.w);
            lr[q * 8 + s] = L;
        }
    }
}

// K4: EMA counts
__global__ void counts_kernel(const float* __restrict__ cc, float* __restrict__ outc) {
    int k = blockIdx.x * blockDim.x + threadIdx.x;
    if (k < NC) outc[k] = 0.99f * cc[k] + 0.01f * (float)g_hist[k];
}

// ---------------------------------------------------------------------------
extern "C" void kernel_launch(void* const* d_in, const int* in_sizes, int n_in,
                              void* d_out, int out_size) {
    const float* x  = (const float*)d_in[0];
    const float* cb = (const float*)d_in[1];
    const float* cc = (const float*)d_in[2];
    float* out = (float*)d_out;

    cudaFuncSetAttribute(approx_kernel,
                         cudaFuncAttributeMaxDynamicSharedMemorySize, SM_TOTAL);

    init_kernel<<<384, 256>>>(x, cb, out + OFF_CB);
    approx_kernel<<<NROWS / BM, 256, SM_TOTAL>>>(x);
    rescore_gather_kernel<<<NROWS * 32 / 256, 256>>>(x, cb, out + OFF_Q, out + OFF_L, out + OFF_NN);
    counts_kernel<<<(NC + 255) / 256, 256>>>(cc, out + OFF_CNT);
}